// round 12
// baseline (speedup 1.0000x reference)
#include <cuda_runtime.h>
#include <cuda_fp16.h>
#include <math.h>

#define NN 50000
#define EE 800000
#define DD 64
#define FIN 128
#define LL 8
#define NSLOPE 0.2f
#define BNEPS 1e-5f
#define NWARPS 8
#define GW (NN / NWARPS)        // 6250 exact
#define SCAN_B 98
#define NSTAT 640               // 128 input BN + 8*64 layer BN

typedef unsigned long long ull;

// ---------------- f32x2 packed helpers ----------------
__device__ __forceinline__ ull pack2(float lo, float hi) {
    ull r; asm("mov.b64 %0, {%1,%2};" : "=l"(r) : "f"(lo), "f"(hi)); return r;
}
__device__ __forceinline__ float2 unpack2(ull v) {
    float2 f; asm("mov.b64 {%0,%1}, %2;" : "=f"(f.x), "=f"(f.y) : "l"(v)); return f;
}
#define FFMA2(d, a, b, c) \
    asm("fma.rn.f32x2 %0, %1, %2, %3;" : "=l"(d) : "l"(a), "l"(b), "l"(c))

// ---------------- scratch ----------------
__device__ float g_dinv[NN];
__device__ int   g_cnt[NN];
__device__ int   g_cursor[NN];
__device__ int   g_offs[NN + 1];
__device__ int   g_part[128];
__device__ int   g_partpref[128];
__device__ int2  g_csr[EE];
__device__ float g_t[(size_t)NN * FIN];
__device__ float g_fused[(size_t)NN * DD];
__device__ __half2 g_mh[(size_t)NN * 32];   // m matrix, fp16x2 packed (cols 2c,2c+1)
__device__ float g_agg[(size_t)NN * DD];
__device__ float g_sum[NSTAT];
__device__ float g_sumsq[NSTAT];

__device__ __forceinline__ float* buf(int id) {
    switch (id) {
        case 0: return g_t;
        case 1: return g_fused;
        default: return g_agg;
    }
}

// ---------------- prep / CSR build ----------------
__global__ void k_prep() {
    int i = blockIdx.x * blockDim.x + threadIdx.x;
    if (i < NN) { g_cnt[i] = 0; g_cursor[i] = 0; }
    if (i < NSTAT) { g_sum[i] = 0.0f; g_sumsq[i] = 0.0f; }
}

__global__ void k_count(const int* __restrict__ ei) {
    int e = blockIdx.x * blockDim.x + threadIdx.x;
    if (e < EE) atomicAdd(&g_cnt[ei[EE + e]], 1);
}

__global__ void __launch_bounds__(512) k_scanA() {
    __shared__ int sh[512];
    int t = threadIdx.x;
    int i = blockIdx.x * 512 + t;
    sh[t] = (i < NN) ? g_cnt[i] : 0;
    __syncthreads();
    for (int off = 256; off >= 1; off >>= 1) {
        if (t < off) sh[t] += sh[t + off];
        __syncthreads();
    }
    if (t == 0) g_part[blockIdx.x] = sh[0];
}

__global__ void __launch_bounds__(128) k_scanB() {
    __shared__ int sh[128];
    int t = threadIdx.x;
    int v = (t < SCAN_B) ? g_part[t] : 0;
    sh[t] = v;
    __syncthreads();
    for (int off = 1; off < 128; off <<= 1) {
        int a = (t >= off) ? sh[t - off] : 0;
        __syncthreads();
        sh[t] += a;
        __syncthreads();
    }
    g_partpref[t] = sh[t] - v;
    if (t == SCAN_B - 1) g_offs[NN] = sh[t];
}

__global__ void __launch_bounds__(512) k_scanC() {
    __shared__ int sh[512];
    int t = threadIdx.x;
    int i = blockIdx.x * 512 + t;
    int v = (i < NN) ? g_cnt[i] : 0;
    sh[t] = v;
    __syncthreads();
    for (int off = 1; off < 512; off <<= 1) {
        int a = (t >= off) ? sh[t - off] : 0;
        __syncthreads();
        sh[t] += a;
        __syncthreads();
    }
    if (i < NN) {
        g_offs[i] = g_partpref[blockIdx.x] + sh[t] - v;
        g_dinv[i] = rsqrtf((float)(v + 1));
    }
}

__global__ void k_fill(const int* __restrict__ ei) {
    int e = blockIdx.x * blockDim.x + threadIdx.x;
    if (e < EE) {
        int s = ei[e];
        int v = ei[EE + e];
        int p = g_offs[v] + atomicAdd(&g_cursor[v], 1);
        g_csr[p] = make_int2(s, __float_as_int(g_dinv[s] * g_dinv[v]));
    }
}

// ---------------- learner (warp-distributed) ----------------
__device__ __forceinline__ float learner(float2 d, int lane,
                                         const float* __restrict__ w1,
                                         const float* __restrict__ b1,
                                         const float* __restrict__ w2,
                                         const float* __restrict__ b2) {
    float4 w1a = ((const float4*)w1)[2 * lane];
    float4 w1b = ((const float4*)w1)[2 * lane + 1];
    float4 p;
    p.x = d.x * w1a.x + d.y * w1b.x;
    p.y = d.x * w1a.y + d.y * w1b.y;
    p.z = d.x * w1a.z + d.y * w1b.z;
    p.w = d.x * w1a.w + d.y * w1b.w;
#pragma unroll
    for (int off = 16; off >= 1; off >>= 1) {
        p.x += __shfl_xor_sync(0xffffffffu, p.x, off);
        p.y += __shfl_xor_sync(0xffffffffu, p.y, off);
        p.z += __shfl_xor_sync(0xffffffffu, p.z, off);
        p.w += __shfl_xor_sync(0xffffffffu, p.w, off);
    }
    float4 bb1 = *((const float4*)b1);
    p.x += bb1.x; p.y += bb1.y; p.z += bb1.z; p.w += bb1.w;
    p.x = p.x > 0.0f ? p.x : NSLOPE * p.x;
    p.y = p.y > 0.0f ? p.y : NSLOPE * p.y;
    p.z = p.z > 0.0f ? p.z : NSLOPE * p.z;
    p.w = p.w > 0.0f ? p.w : NSLOPE * p.w;
    float4 ww2 = *((const float4*)w2);
    float z = p.x * ww2.x + p.y * ww2.y + p.z * ww2.z + p.w * ww2.w + b2[0];
    return 1.0f / (1.0f + __expf(-z));
}

// ---------------- N=128 GEMM: 64x128 tile, 4 rows x 8 cols/thread, f32x2 ----------------
// 256 threads (16x16): tx = col group (8 cols), ty = row group (4 rows).
// smem: As 8448 + Ws 16384 + stats 16384 = 41216 B < 48 KB.
template <int K, int POST_RELU, int STATS, int ABUF>
__global__ void __launch_bounds__(256) k_gemm_n128(const float* __restrict__ Aext,
                                                   const float* __restrict__ W,
                                                   const float* __restrict__ bias,
                                                   int slotoff) {
    const float* A = (ABUF < 0) ? Aext : buf(ABUF);
    float* O = g_t;
    __shared__ __align__(16) float As[32][66];     // [k][row 0..63]
    __shared__ __align__(16) float Ws[32][128];    // [k][col]
    __shared__ __align__(16) float Ssum[16][128];
    __shared__ __align__(16) float Ssq[16][128];
    int tid = threadIdx.x;
    int tx = tid & 15, ty = tid >> 4;
    int row0 = blockIdx.x * 64;

    float4 b0 = ((const float4*)bias)[2 * tx];
    float4 b1 = ((const float4*)bias)[2 * tx + 1];
    ull acc[2][8];
#pragma unroll
    for (int p = 0; p < 2; p++) {
        acc[p][0] = pack2(b0.x, b0.x); acc[p][1] = pack2(b0.y, b0.y);
        acc[p][2] = pack2(b0.z, b0.z); acc[p][3] = pack2(b0.w, b0.w);
        acc[p][4] = pack2(b1.x, b1.x); acc[p][5] = pack2(b1.y, b1.y);
        acc[p][6] = pack2(b1.z, b1.z); acc[p][7] = pack2(b1.w, b1.w);
    }

#pragma unroll
    for (int kc = 0; kc < K / 32; kc++) {
        if (kc > 0) __syncthreads();
        // stage A chunk transposed: 64 rows x 32 k (512 float4 loads)
        for (int i = tid; i < 512; i += 256) {
            int r = i >> 3, c4 = i & 7;
            int gr = row0 + r; if (gr >= NN) gr = NN - 1;
            float4 v = ((const float4*)(A + (size_t)gr * K + kc * 32))[c4];
            As[4 * c4 + 0][r] = v.x;
            As[4 * c4 + 1][r] = v.y;
            As[4 * c4 + 2][r] = v.z;
            As[4 * c4 + 3][r] = v.w;
        }
        // stage W chunk: 32 k x 128 cols (1024 float4)
        for (int i = tid; i < 1024; i += 256) {
            int k = i >> 5, c4 = i & 31;
            float4 v = ((const float4*)(W + (size_t)(kc * 32 + k) * 128))[c4];
            *((float4*)&Ws[k][c4 * 4]) = v;
        }
        __syncthreads();
#pragma unroll 8
        for (int k = 0; k < 32; k++) {
            ull a[2];
            a[0] = *((const ull*)&As[k][ty * 4]);
            a[1] = *((const ull*)&As[k][ty * 4 + 2]);
            float4 w0 = *((const float4*)&Ws[k][tx * 8]);
            float4 w1 = *((const float4*)&Ws[k][tx * 8 + 4]);
            ull wd[8];
            wd[0] = pack2(w0.x, w0.x); wd[1] = pack2(w0.y, w0.y);
            wd[2] = pack2(w0.z, w0.z); wd[3] = pack2(w0.w, w0.w);
            wd[4] = pack2(w1.x, w1.x); wd[5] = pack2(w1.y, w1.y);
            wd[6] = pack2(w1.z, w1.z); wd[7] = pack2(w1.w, w1.w);
#pragma unroll
            for (int p = 0; p < 2; p++)
#pragma unroll
                for (int c = 0; c < 8; c++)
                    FFMA2(acc[p][c], a[p], wd[c], acc[p][c]);
        }
    }

    // store + optional stats
    float ps[8], pq[8];
#pragma unroll
    for (int c = 0; c < 8; c++) { ps[c] = 0.0f; pq[c] = 0.0f; }
#pragma unroll
    for (int p = 0; p < 2; p++) {
        float2 cc[8];
#pragma unroll
        for (int c = 0; c < 8; c++) {
            cc[c] = unpack2(acc[p][c]);
            if (POST_RELU) { cc[c].x = fmaxf(cc[c].x, 0.0f); cc[c].y = fmaxf(cc[c].y, 0.0f); }
        }
        int gr0 = row0 + ty * 4 + 2 * p;
        if (gr0 < NN) {
            *((float4*)(O + (size_t)gr0 * FIN + tx * 8)) =
                make_float4(cc[0].x, cc[1].x, cc[2].x, cc[3].x);
            *((float4*)(O + (size_t)gr0 * FIN + tx * 8 + 4)) =
                make_float4(cc[4].x, cc[5].x, cc[6].x, cc[7].x);
            if (STATS)
#pragma unroll
                for (int c = 0; c < 8; c++) { ps[c] += cc[c].x; pq[c] += cc[c].x * cc[c].x; }
        }
        if (gr0 + 1 < NN) {
            *((float4*)(O + (size_t)(gr0 + 1) * FIN + tx * 8)) =
                make_float4(cc[0].y, cc[1].y, cc[2].y, cc[3].y);
            *((float4*)(O + (size_t)(gr0 + 1) * FIN + tx * 8 + 4)) =
                make_float4(cc[4].y, cc[5].y, cc[6].y, cc[7].y);
            if (STATS)
#pragma unroll
                for (int c = 0; c < 8; c++) { ps[c] += cc[c].y; pq[c] += cc[c].y * cc[c].y; }
        }
    }
    if (STATS) {
        __syncthreads();
        *((float4*)&Ssum[ty][tx * 8]) = make_float4(ps[0], ps[1], ps[2], ps[3]);
        *((float4*)&Ssum[ty][tx * 8 + 4]) = make_float4(ps[4], ps[5], ps[6], ps[7]);
        *((float4*)&Ssq[ty][tx * 8]) = make_float4(pq[0], pq[1], pq[2], pq[3]);
        *((float4*)&Ssq[ty][tx * 8 + 4]) = make_float4(pq[4], pq[5], pq[6], pq[7]);
        __syncthreads();
        if (tid < 128) {
            float s = 0.0f, q = 0.0f;
#pragma unroll
            for (int t = 0; t < 16; t++) { s += Ssum[t][tid]; q += Ssq[t][tid]; }
            atomicAdd(&g_sum[slotoff + tid], s);
            atomicAdd(&g_sumsq[slotoff + tid], q);
        }
    }
}

// ---------------- N=64 GEMM: 128x64 tile, 8x4/thread, f32x2 ----------------
template <int K, int PRE_BN, int POST_RELU, int ABUF, int OBUF>
__global__ void __launch_bounds__(256) k_gemm(const float* __restrict__ Aext,
                                              const float* __restrict__ W, int ldw,
                                              const float* __restrict__ bias,
                                              float* __restrict__ Oext, int ldo,
                                              const float* __restrict__ gam,
                                              const float* __restrict__ bet, int bnslot) {
    const float* A = (ABUF < 0) ? Aext : buf(ABUF);
    float* O = (OBUF < 0) ? Oext : buf(OBUF);
    __shared__ __align__(16) float As[32][130];   // [k][row 0..127]
    __shared__ __align__(16) float Ws[32][64];    // [k][col]
    __shared__ float SC[FIN], SH[FIN];
    int tid = threadIdx.x;
    int tx = tid & 15, ty = tid >> 4;
    int row0 = blockIdx.x * 128;

    if (PRE_BN) {
        if (tid < K) {
            const float ninv = 1.0f / (float)NN;
            float mean = g_sum[bnslot + tid] * ninv;
            float var = g_sumsq[bnslot + tid] * ninv - mean * mean;
            float sc = gam[tid] * rsqrtf(var + BNEPS);
            SC[tid] = sc;
            SH[tid] = bet[tid] - mean * sc;
        }
        __syncthreads();
    }

    float4 bv = ((const float4*)bias)[tx];
    ull acc[4][4];
#pragma unroll
    for (int p = 0; p < 4; p++) {
        acc[p][0] = pack2(bv.x, bv.x);
        acc[p][1] = pack2(bv.y, bv.y);
        acc[p][2] = pack2(bv.z, bv.z);
        acc[p][3] = pack2(bv.w, bv.w);
    }

#pragma unroll
    for (int kc = 0; kc < K / 32; kc++) {
        if (kc > 0) __syncthreads();
        for (int i = tid; i < 1024; i += 256) {
            int r = i >> 3, c4 = i & 7;
            int gr = row0 + r; if (gr >= NN) gr = NN - 1;
            float4 v = ((const float4*)(A + (size_t)gr * K + kc * 32))[c4];
            if (PRE_BN) {
                int c = kc * 32 + c4 * 4;
                v.x = fmaxf(v.x * SC[c] + SH[c], 0.0f);
                v.y = fmaxf(v.y * SC[c + 1] + SH[c + 1], 0.0f);
                v.z = fmaxf(v.z * SC[c + 2] + SH[c + 2], 0.0f);
                v.w = fmaxf(v.w * SC[c + 3] + SH[c + 3], 0.0f);
            }
            As[4 * c4 + 0][r] = v.x;
            As[4 * c4 + 1][r] = v.y;
            As[4 * c4 + 2][r] = v.z;
            As[4 * c4 + 3][r] = v.w;
        }
        for (int i = tid; i < 512; i += 256) {
            int k = i >> 4, c4 = i & 15;
            float4 v = ((const float4*)(W + (size_t)(kc * 32 + k) * ldw))[c4];
            *((float4*)&Ws[k][c4 * 4]) = v;
        }
        __syncthreads();
#pragma unroll 8
        for (int k = 0; k < 32; k++) {
            ull a[4];
#pragma unroll
            for (int p = 0; p < 4; p++)
                a[p] = *((const ull*)&As[k][ty * 8 + 2 * p]);
            float4 w = *((const float4*)&Ws[k][tx * 4]);
            ull wd[4];
            wd[0] = pack2(w.x, w.x); wd[1] = pack2(w.y, w.y);
            wd[2] = pack2(w.z, w.z); wd[3] = pack2(w.w, w.w);
#pragma unroll
            for (int p = 0; p < 4; p++)
#pragma unroll
                for (int c = 0; c < 4; c++)
                    FFMA2(acc[p][c], a[p], wd[c], acc[p][c]);
        }
    }

#pragma unroll
    for (int p = 0; p < 4; p++) {
        float2 c0 = unpack2(acc[p][0]), c1 = unpack2(acc[p][1]);
        float2 c2 = unpack2(acc[p][2]), c3 = unpack2(acc[p][3]);
        if (POST_RELU) {
            c0.x = fmaxf(c0.x, 0.0f); c0.y = fmaxf(c0.y, 0.0f);
            c1.x = fmaxf(c1.x, 0.0f); c1.y = fmaxf(c1.y, 0.0f);
            c2.x = fmaxf(c2.x, 0.0f); c2.y = fmaxf(c2.y, 0.0f);
            c3.x = fmaxf(c3.x, 0.0f); c3.y = fmaxf(c3.y, 0.0f);
        }
        int gr0 = row0 + ty * 8 + 2 * p;
        if (gr0 < NN)
            *((float4*)(O + (size_t)gr0 * ldo + tx * 4)) = make_float4(c0.x, c1.x, c2.x, c3.x);
        if (gr0 + 1 < NN)
            *((float4*)(O + (size_t)(gr0 + 1) * ldo + tx * 4)) = make_float4(c0.y, c1.y, c2.y, c3.y);
    }
}

// ---------------- gather (fp16 m reads) with fused stats ----------------
__global__ void __launch_bounds__(256) k_gather(const float* __restrict__ bbL, int slotoff) {
    int lane = threadIdx.x & 31, wid = threadIdx.x >> 5;
    int v = blockIdx.x * NWARPS + wid;
    float dv = g_dinv[v];
    float2 mv = __half22float2(g_mh[(size_t)v * 32 + lane]);
    float ws = dv * dv;
    float2 acc = make_float2(mv.x * ws, mv.y * ws);
    int beg = g_offs[v], end = g_offs[v + 1];
    int j = beg;
    for (; j + 8 <= end; j += 8) {
        int2 e[8];
        __half2 mm[8];
#pragma unroll
        for (int u = 0; u < 8; u++) e[u] = g_csr[j + u];
#pragma unroll
        for (int u = 0; u < 8; u++)
            mm[u] = g_mh[(size_t)e[u].x * 32 + lane];
#pragma unroll
        for (int u = 0; u < 8; u++) {
            float w = __int_as_float(e[u].y);
            float2 mf = __half22float2(mm[u]);
            acc.x = fmaf(w, mf.x, acc.x);
            acc.y = fmaf(w, mf.y, acc.y);
        }
    }
    for (; j < end; j++) {
        int2 e = g_csr[j];
        float w = __int_as_float(e.y);
        float2 mf = __half22float2(g_mh[(size_t)e.x * 32 + lane]);
        acc.x = fmaf(w, mf.x, acc.x);
        acc.y = fmaf(w, mf.y, acc.y);
    }
    float2 b = ((const float2*)bbL)[lane];
    acc.x += b.x;
    acc.y += b.y;
    ((float2*)(g_agg + (size_t)v * DD))[lane] = acc;
    __shared__ float s_sum[8 * 64], s_sq[8 * 64];
    ((float2*)(s_sum + wid * 64))[lane] = acc;
    ((float2*)(s_sq + wid * 64))[lane] = make_float2(acc.x * acc.x, acc.y * acc.y);
    __syncthreads();
    int tid = threadIdx.x;
    if (tid < 64) {
        float s = 0.0f;
#pragma unroll
        for (int w = 0; w < 8; w++) s += s_sum[w * 64 + tid];
        atomicAdd(&g_sum[slotoff + tid], s);
    } else if (tid < 128) {
        int c = tid - 64;
        float q = 0.0f;
#pragma unroll
        for (int w = 0; w < 8; w++) q += s_sq[w * 64 + c];
        atomicAdd(&g_sumsq[slotoff + c], q);
    }
}

// ---------------- post: elementwise+learner for 64 nodes, then rb-GEMM to g_mh ----------------
template <int MODE, int LAST>
__global__ void __launch_bounds__(256) k_post(int slotoff,
                                              const float* __restrict__ gam,
                                              const float* __restrict__ bet,
                                              const float* __restrict__ lw1,
                                              const float* __restrict__ lb1,
                                              const float* __restrict__ lw2,
                                              const float* __restrict__ lb2,
                                              const float* __restrict__ bwn) {
    __shared__ __align__(16) float Hs[64][66];   // [k][node]
    __shared__ __align__(16) float Ws[64][64];
    int tid = threadIdx.x;
    int lane = tid & 31, wid = tid >> 5;
    if (!LAST) {
        for (int i = tid; i < 1024; i += 256) {
            int k = i >> 4, c4 = i & 15;
            *((float4*)&Ws[k][c4 * 4]) = ((const float4*)(bwn + (size_t)k * 64))[c4];
        }
    }
    float scx = 1.0f, scy = 1.0f, shx = 0.0f, shy = 0.0f;
    if (MODE == 1) {
        const float ninv = 1.0f / (float)NN;
        float2 su = ((const float2*)(g_sum + slotoff))[lane];
        float2 sq = ((const float2*)(g_sumsq + slotoff))[lane];
        float2 gm = ((const float2*)gam)[lane];
        float2 bt = ((const float2*)bet)[lane];
        float mx = su.x * ninv, my = su.y * ninv;
        scx = gm.x * rsqrtf(sq.x * ninv - mx * mx + BNEPS);
        scy = gm.y * rsqrtf(sq.y * ninv - my * my + BNEPS);
        shx = bt.x - mx * scx;
        shy = bt.y - my * scy;
    }
#pragma unroll
    for (int n = 0; n < 8; n++) {
        int node = blockIdx.x * 64 + wid * 8 + n;
        float2 hv = make_float2(0.0f, 0.0f);
        if (node < NN) {
            float2 a = ((const float2*)(g_agg + (size_t)node * DD))[lane];
            float2 hn;
            if (MODE == 1) {
                hn.x = fmaxf(a.x * scx + shx, 0.0f);
                hn.y = fmaxf(a.y * scy + shy, 0.0f);
            } else {
                hn = a;
            }
            float2 fo = make_float2(0.0f, 0.0f);
            float2 d = hn;
            if (MODE == 1) {
                fo = ((const float2*)(g_fused + (size_t)node * DD))[lane];
                d.x = hn.x - fo.x;
                d.y = hn.y - fo.y;
            }
            float s = learner(d, lane, lw1, lb1, lw2, lb2);
            hv = make_float2(hn.x * s, hn.y * s);
            float2 fn = make_float2(fo.x + hv.x, fo.y + hv.y);
            ((float2*)(g_fused + (size_t)node * DD))[lane] = fn;
        }
        Hs[2 * lane][wid * 8 + n] = hv.x;
        Hs[2 * lane + 1][wid * 8 + n] = hv.y;
    }
    __syncthreads();
    if (LAST) return;
    // GEMM: m[64 nodes] = Hs^T @ Ws, stored fp16 to g_mh
    int tx = tid & 15, ty = tid >> 4;
    ull acc[2][4];
#pragma unroll
    for (int p = 0; p < 2; p++)
#pragma unroll
        for (int c = 0; c < 4; c++) acc[p][c] = 0ull;
#pragma unroll 8
    for (int k = 0; k < 64; k++) {
        ull a0 = *((const ull*)&Hs[k][ty * 4]);
        ull a1 = *((const ull*)&Hs[k][ty * 4 + 2]);
        float4 w = *((const float4*)&Ws[k][tx * 4]);
        ull wd[4];
        wd[0] = pack2(w.x, w.x); wd[1] = pack2(w.y, w.y);
        wd[2] = pack2(w.z, w.z); wd[3] = pack2(w.w, w.w);
#pragma unroll
        for (int c = 0; c < 4; c++) {
            FFMA2(acc[0][c], a0, wd[c], acc[0][c]);
            FFMA2(acc[1][c], a1, wd[c], acc[1][c]);
        }
    }
#pragma unroll
    for (int p = 0; p < 2; p++) {
        float2 c0 = unpack2(acc[p][0]), c1 = unpack2(acc[p][1]);
        float2 c2 = unpack2(acc[p][2]), c3 = unpack2(acc[p][3]);
        int gr0 = blockIdx.x * 64 + ty * 4 + 2 * p;
        if (gr0 < NN) {
            __half2 p0 = __floats2half2_rn(c0.x, c1.x);
            __half2 p1 = __floats2half2_rn(c2.x, c3.x);
            uint2 pk = make_uint2(*(unsigned*)&p0, *(unsigned*)&p1);
            *((uint2*)&g_mh[(size_t)gr0 * 32 + tx * 2]) = pk;
        }
        if (gr0 + 1 < NN) {
            __half2 p0 = __floats2half2_rn(c0.y, c1.y);
            __half2 p1 = __floats2half2_rn(c2.y, c3.y);
            uint2 pk = make_uint2(*(unsigned*)&p0, *(unsigned*)&p1);
            *((uint2*)&g_mh[(size_t)(gr0 + 1) * 32 + tx * 2]) = pk;
        }
    }
}

// ---------------- host orchestration ----------------
extern "C" void kernel_launch(void* const* d_in, const int* in_sizes, int n_in,
                              void* d_out, int out_size) {
    const float* x      = (const float*)d_in[0];
    const int*   ei     = (const int*)d_in[1];
    const float* im_w1  = (const float*)d_in[2];
    const float* im_b1  = (const float*)d_in[3];
    const float* im_g1  = (const float*)d_in[4];
    const float* im_be1 = (const float*)d_in[5];
    const float* im_w2  = (const float*)d_in[6];
    const float* im_b2  = (const float*)d_in[7];
    const float* lw1    = (const float*)d_in[8];
    const float* lb1    = (const float*)d_in[9];
    const float* lw2    = (const float*)d_in[10];
    const float* lb2    = (const float*)d_in[11];
    const float* bw     = (const float*)d_in[12];
    const float* bb     = (const float*)d_in[13];
    const float* bg     = (const float*)d_in[14];
    const float* bbe    = (const float*)d_in[15];
    const float* om_w1  = (const float*)d_in[16];
    const float* om_b1  = (const float*)d_in[17];
    const float* om_w2  = (const float*)d_in[18];
    const float* om_b2  = (const float*)d_in[19];
    float* outp = (float*)d_out;

    const int NB = (NN + 255) / 256;
    const int EB = (EE + 255) / 256;
    const int G128 = (NN + 127) / 128;  // 391 tiles (N=64 gemm)
    const int G64 = (NN + 63) / 64;     // 782 tiles (N=128 gemm / k_post)

    // 1-3: prep + degree count + scanA
    k_prep<<<NB, 256>>>();
    k_count<<<EB, 256>>>(ei);
    k_scanA<<<SCAN_B, 512>>>();
    // 4: merged input-map GEMM (all 128 cols; profiled slot)
    k_gemm_n128<128, 0, 1, -1><<<G64, 256>>>(x, im_w1, im_b1, 0);
    // 5-7: finish CSR build
    k_scanB<<<1, 128>>>();
    k_scanC<<<SCAN_B, 512>>>();
    k_fill<<<EB, 256>>>(ei);
    // 8: input-map mid GEMM with fused BN+relu (g_t -> g_agg holds h)
    k_gemm<128, 1, 0, 0, 2><<<G128, 256>>>(nullptr, im_w2, 64, im_b2, nullptr, 64,
                                           im_g1, im_be1, 0);
    // 9: learner0 + fused init + m = hv @ bw[0] (fp16)
    k_post<0, 0><<<G64, 256>>>(0, nullptr, nullptr, lw1, lb1, lw2, lb2, bw);
    // 10-25: 8 GCN blocks
    for (int li = 0; li < LL; li++) {
        k_gather<<<GW, 256>>>(bb + 64 * li, 128 + 64 * li);
        if (li < LL - 1) {
            k_post<1, 0><<<G64, 256>>>(128 + 64 * li, bg + 64 * li, bbe + 64 * li,
                                       lw1 + (size_t)(li + 1) * 256, lb1 + (li + 1) * 4,
                                       lw2 + (li + 1) * 4, lb2 + (li + 1),
                                       bw + (size_t)(li + 1) * 4096);
        } else {
            k_post<1, 1><<<G64, 256>>>(128 + 64 * li, bg + 64 * li, bbe + 64 * li,
                                       lw1 + (size_t)(li + 1) * 256, lb1 + (li + 1) * 4,
                                       lw2 + (li + 1) * 4, lb2 + (li + 1), nullptr);
        }
    }
    // 26: merged output-map GEMM 1 (fused -> g_t, relu, 128 cols)
    k_gemm_n128<64, 1, 0, 1><<<G64, 256>>>(nullptr, om_w1, om_b1, 0);
    // 27: output-map GEMM 2 (g_t -> out)
    k_gemm<128, 0, 0, 0, -1><<<G128, 256>>>(nullptr, om_w2, 64, om_b2, outp, 64,
                                            nullptr, nullptr, 0);
}

// round 15
// speedup vs baseline: 1.0616x; 1.0616x over previous
#include <cuda_runtime.h>
#include <cuda_fp16.h>
#include <math.h>

#define NN 50000
#define EE 800000
#define DD 64
#define FIN 128
#define LL 8
#define NSLOPE 0.2f
#define BNEPS 1e-5f
#define NWARPS 8
#define GW (NN / NWARPS)        // 6250 exact
#define SCAN_B 98
#define NSTAT 640               // 128 input BN + 8*64 layer BN

typedef unsigned long long ull;

// ---------------- f32x2 packed helpers ----------------
__device__ __forceinline__ ull pack2(float lo, float hi) {
    ull r; asm("mov.b64 %0, {%1,%2};" : "=l"(r) : "f"(lo), "f"(hi)); return r;
}
__device__ __forceinline__ float2 unpack2(ull v) {
    float2 f; asm("mov.b64 {%0,%1}, %2;" : "=f"(f.x), "=f"(f.y) : "l"(v)); return f;
}
#define FFMA2(d, a, b, c) \
    asm("fma.rn.f32x2 %0, %1, %2, %3;" : "=l"(d) : "l"(a), "l"(b), "l"(c))

// ---------------- scratch ----------------
__device__ float g_dinv[NN];
__device__ int   g_cnt[NN];
__device__ int   g_cursor[NN];
__device__ int   g_offs[NN + 1];
__device__ int   g_part[128];
__device__ int   g_partpref[128];
__device__ int2  g_csr[EE];
__device__ float g_t[(size_t)NN * FIN];
__device__ float g_fused[(size_t)NN * DD];
__device__ __half2 g_mh[(size_t)NN * 32];   // m matrix, fp16x2 packed (cols 2c,2c+1)
__device__ float g_agg[(size_t)NN * DD];
__device__ float g_sum[NSTAT];
__device__ float g_sumsq[NSTAT];

__device__ __forceinline__ float* buf(int id) {
    switch (id) {
        case 0: return g_t;
        case 1: return g_fused;
        default: return g_agg;
    }
}

// ---------------- prep / CSR build ----------------
__global__ void k_prep() {
    int i = blockIdx.x * blockDim.x + threadIdx.x;
    if (i < NN) { g_cnt[i] = 0; g_cursor[i] = 0; }
    if (i < NSTAT) { g_sum[i] = 0.0f; g_sumsq[i] = 0.0f; }
}

__global__ void k_count(const int* __restrict__ ei) {
    int e = blockIdx.x * blockDim.x + threadIdx.x;
    if (e < EE) atomicAdd(&g_cnt[ei[EE + e]], 1);
}

__global__ void __launch_bounds__(512) k_scanA() {
    __shared__ int sh[512];
    int t = threadIdx.x;
    int i = blockIdx.x * 512 + t;
    sh[t] = (i < NN) ? g_cnt[i] : 0;
    __syncthreads();
    for (int off = 256; off >= 1; off >>= 1) {
        if (t < off) sh[t] += sh[t + off];
        __syncthreads();
    }
    if (t == 0) g_part[blockIdx.x] = sh[0];
}

__global__ void __launch_bounds__(128) k_scanB() {
    __shared__ int sh[128];
    int t = threadIdx.x;
    int v = (t < SCAN_B) ? g_part[t] : 0;
    sh[t] = v;
    __syncthreads();
    for (int off = 1; off < 128; off <<= 1) {
        int a = (t >= off) ? sh[t - off] : 0;
        __syncthreads();
        sh[t] += a;
        __syncthreads();
    }
    g_partpref[t] = sh[t] - v;
    if (t == SCAN_B - 1) g_offs[NN] = sh[t];
}

__global__ void __launch_bounds__(512) k_scanC() {
    __shared__ int sh[512];
    int t = threadIdx.x;
    int i = blockIdx.x * 512 + t;
    int v = (i < NN) ? g_cnt[i] : 0;
    sh[t] = v;
    __syncthreads();
    for (int off = 1; off < 512; off <<= 1) {
        int a = (t >= off) ? sh[t - off] : 0;
        __syncthreads();
        sh[t] += a;
        __syncthreads();
    }
    if (i < NN) {
        g_offs[i] = g_partpref[blockIdx.x] + sh[t] - v;
        g_dinv[i] = rsqrtf((float)(v + 1));
    }
}

__global__ void k_fill(const int* __restrict__ ei) {
    int e = blockIdx.x * blockDim.x + threadIdx.x;
    if (e < EE) {
        int s = ei[e];
        int v = ei[EE + e];
        int p = g_offs[v] + atomicAdd(&g_cursor[v], 1);
        g_csr[p] = make_int2(s, __float_as_int(g_dinv[s] * g_dinv[v]));
    }
}

// ---------------- learner (warp-distributed) ----------------
__device__ __forceinline__ float learner(float2 d, int lane,
                                         const float* __restrict__ w1,
                                         const float* __restrict__ b1,
                                         const float* __restrict__ w2,
                                         const float* __restrict__ b2) {
    float4 w1a = ((const float4*)w1)[2 * lane];
    float4 w1b = ((const float4*)w1)[2 * lane + 1];
    float4 p;
    p.x = d.x * w1a.x + d.y * w1b.x;
    p.y = d.x * w1a.y + d.y * w1b.y;
    p.z = d.x * w1a.z + d.y * w1b.z;
    p.w = d.x * w1a.w + d.y * w1b.w;
#pragma unroll
    for (int off = 16; off >= 1; off >>= 1) {
        p.x += __shfl_xor_sync(0xffffffffu, p.x, off);
        p.y += __shfl_xor_sync(0xffffffffu, p.y, off);
        p.z += __shfl_xor_sync(0xffffffffu, p.z, off);
        p.w += __shfl_xor_sync(0xffffffffu, p.w, off);
    }
    float4 bb1 = *((const float4*)b1);
    p.x += bb1.x; p.y += bb1.y; p.z += bb1.z; p.w += bb1.w;
    p.x = p.x > 0.0f ? p.x : NSLOPE * p.x;
    p.y = p.y > 0.0f ? p.y : NSLOPE * p.y;
    p.z = p.z > 0.0f ? p.z : NSLOPE * p.z;
    p.w = p.w > 0.0f ? p.w : NSLOPE * p.w;
    float4 ww2 = *((const float4*)w2);
    float z = p.x * ww2.x + p.y * ww2.y + p.z * ww2.z + p.w * ww2.w + b2[0];
    return 1.0f / (1.0f + __expf(-z));
}

// ---------------- GEMM: 128x64 tile, 8x4/thread, f32x2, K chunked by 32 ----------------
template <int K, int PRE_BN, int POST_RELU, int STATS, int ABUF, int OBUF>
__global__ void __launch_bounds__(256) k_gemm(const float* __restrict__ Aext,
                                              const float* __restrict__ W, int ldw,
                                              const float* __restrict__ bias,
                                              float* __restrict__ Oext, int ldo, int ooff,
                                              int slotoff,
                                              const float* __restrict__ gam,
                                              const float* __restrict__ bet, int bnslot) {
    const float* A = (ABUF < 0) ? Aext : buf(ABUF);
    float* O = ((OBUF < 0) ? Oext : buf(OBUF)) + ooff;
    __shared__ __align__(16) float As[32][130];   // [k][row 0..127]
    __shared__ __align__(16) float Ws[32][64];    // [k][col]
    __shared__ __align__(16) float Ssum[16][64];
    __shared__ __align__(16) float Ssq[16][64];
    __shared__ float SC[FIN], SH[FIN];
    int tid = threadIdx.x;
    int tx = tid & 15, ty = tid >> 4;
    int row0 = blockIdx.x * 128;

    if (PRE_BN) {
        if (tid < K) {
            const float ninv = 1.0f / (float)NN;
            float mean = g_sum[bnslot + tid] * ninv;
            float var = g_sumsq[bnslot + tid] * ninv - mean * mean;
            float sc = gam[tid] * rsqrtf(var + BNEPS);
            SC[tid] = sc;
            SH[tid] = bet[tid] - mean * sc;
        }
        __syncthreads();
    }

    float4 bv = ((const float4*)bias)[tx];
    ull acc[4][4];
#pragma unroll
    for (int p = 0; p < 4; p++) {
        acc[p][0] = pack2(bv.x, bv.x);
        acc[p][1] = pack2(bv.y, bv.y);
        acc[p][2] = pack2(bv.z, bv.z);
        acc[p][3] = pack2(bv.w, bv.w);
    }

#pragma unroll
    for (int kc = 0; kc < K / 32; kc++) {
        if (kc > 0) __syncthreads();
        for (int i = tid; i < 1024; i += 256) {
            int r = i >> 3, c4 = i & 7;
            int gr = row0 + r; if (gr >= NN) gr = NN - 1;
            float4 v = ((const float4*)(A + (size_t)gr * K + kc * 32))[c4];
            if (PRE_BN) {
                int c = kc * 32 + c4 * 4;
                v.x = fmaxf(v.x * SC[c] + SH[c], 0.0f);
                v.y = fmaxf(v.y * SC[c + 1] + SH[c + 1], 0.0f);
                v.z = fmaxf(v.z * SC[c + 2] + SH[c + 2], 0.0f);
                v.w = fmaxf(v.w * SC[c + 3] + SH[c + 3], 0.0f);
            }
            As[4 * c4 + 0][r] = v.x;
            As[4 * c4 + 1][r] = v.y;
            As[4 * c4 + 2][r] = v.z;
            As[4 * c4 + 3][r] = v.w;
        }
        for (int i = tid; i < 512; i += 256) {
            int k = i >> 4, c4 = i & 15;
            float4 v = ((const float4*)(W + (size_t)(kc * 32 + k) * ldw))[c4];
            *((float4*)&Ws[k][c4 * 4]) = v;
        }
        __syncthreads();
#pragma unroll 8
        for (int k = 0; k < 32; k++) {
            ull a[4];
#pragma unroll
            for (int p = 0; p < 4; p++)
                a[p] = *((const ull*)&As[k][ty * 8 + 2 * p]);
            float4 w = *((const float4*)&Ws[k][tx * 4]);
            ull wd[4];
            wd[0] = pack2(w.x, w.x); wd[1] = pack2(w.y, w.y);
            wd[2] = pack2(w.z, w.z); wd[3] = pack2(w.w, w.w);
#pragma unroll
            for (int p = 0; p < 4; p++)
#pragma unroll
                for (int c = 0; c < 4; c++)
                    FFMA2(acc[p][c], a[p], wd[c], acc[p][c]);
        }
    }

    float4 ps = make_float4(0.0f, 0.0f, 0.0f, 0.0f);
    float4 pq = make_float4(0.0f, 0.0f, 0.0f, 0.0f);
#pragma unroll
    for (int p = 0; p < 4; p++) {
        float2 c0 = unpack2(acc[p][0]), c1 = unpack2(acc[p][1]);
        float2 c2 = unpack2(acc[p][2]), c3 = unpack2(acc[p][3]);
        if (POST_RELU) {
            c0.x = fmaxf(c0.x, 0.0f); c0.y = fmaxf(c0.y, 0.0f);
            c1.x = fmaxf(c1.x, 0.0f); c1.y = fmaxf(c1.y, 0.0f);
            c2.x = fmaxf(c2.x, 0.0f); c2.y = fmaxf(c2.y, 0.0f);
            c3.x = fmaxf(c3.x, 0.0f); c3.y = fmaxf(c3.y, 0.0f);
        }
        int gr0 = row0 + ty * 8 + 2 * p;
        if (gr0 < NN) {
            *((float4*)(O + (size_t)gr0 * ldo + tx * 4)) = make_float4(c0.x, c1.x, c2.x, c3.x);
            if (STATS) {
                ps.x += c0.x; ps.y += c1.x; ps.z += c2.x; ps.w += c3.x;
                pq.x += c0.x * c0.x; pq.y += c1.x * c1.x;
                pq.z += c2.x * c2.x; pq.w += c3.x * c3.x;
            }
        }
        if (gr0 + 1 < NN) {
            *((float4*)(O + (size_t)(gr0 + 1) * ldo + tx * 4)) = make_float4(c0.y, c1.y, c2.y, c3.y);
            if (STATS) {
                ps.x += c0.y; ps.y += c1.y; ps.z += c2.y; ps.w += c3.y;
                pq.x += c0.y * c0.y; pq.y += c1.y * c1.y;
                pq.z += c2.y * c2.y; pq.w += c3.y * c3.y;
            }
        }
    }
    if (STATS) {
        __syncthreads();
        *((float4*)&Ssum[ty][tx * 4]) = ps;
        *((float4*)&Ssq[ty][tx * 4]) = pq;
        __syncthreads();
        if (tid < 64) {
            float s = 0.0f;
#pragma unroll
            for (int t = 0; t < 16; t++) s += Ssum[t][tid];
            atomicAdd(&g_sum[slotoff + tid], s);
        } else if (tid < 128) {
            int c = tid - 64;
            float q = 0.0f;
#pragma unroll
            for (int t = 0; t < 16; t++) q += Ssq[t][c];
            atomicAdd(&g_sumsq[slotoff + c], q);
        }
    }
}

// ---------------- gather (fp16 m reads) with fused stats ----------------
__global__ void __launch_bounds__(256) k_gather(const float* __restrict__ bbL, int slotoff) {
    int lane = threadIdx.x & 31, wid = threadIdx.x >> 5;
    int v = blockIdx.x * NWARPS + wid;
    float dv = g_dinv[v];
    float2 mv = __half22float2(g_mh[(size_t)v * 32 + lane]);
    float ws = dv * dv;
    float2 acc = make_float2(mv.x * ws, mv.y * ws);
    int beg = g_offs[v], end = g_offs[v + 1];
    int j = beg;
    for (; j + 8 <= end; j += 8) {
        int2 e[8];
        __half2 mm[8];
#pragma unroll
        for (int u = 0; u < 8; u++) e[u] = g_csr[j + u];
#pragma unroll
        for (int u = 0; u < 8; u++)
            mm[u] = g_mh[(size_t)e[u].x * 32 + lane];
#pragma unroll
        for (int u = 0; u < 8; u++) {
            float w = __int_as_float(e[u].y);
            float2 mf = __half22float2(mm[u]);
            acc.x = fmaf(w, mf.x, acc.x);
            acc.y = fmaf(w, mf.y, acc.y);
        }
    }
    for (; j < end; j++) {
        int2 e = g_csr[j];
        float w = __int_as_float(e.y);
        float2 mf = __half22float2(g_mh[(size_t)e.x * 32 + lane]);
        acc.x = fmaf(w, mf.x, acc.x);
        acc.y = fmaf(w, mf.y, acc.y);
    }
    float2 b = ((const float2*)bbL)[lane];
    acc.x += b.x;
    acc.y += b.y;
    ((float2*)(g_agg + (size_t)v * DD))[lane] = acc;
    __shared__ float s_sum[8 * 64], s_sq[8 * 64];
    ((float2*)(s_sum + wid * 64))[lane] = acc;
    ((float2*)(s_sq + wid * 64))[lane] = make_float2(acc.x * acc.x, acc.y * acc.y);
    __syncthreads();
    int tid = threadIdx.x;
    if (tid < 64) {
        float s = 0.0f;
#pragma unroll
        for (int w = 0; w < 8; w++) s += s_sum[w * 64 + tid];
        atomicAdd(&g_sum[slotoff + tid], s);
    } else if (tid < 128) {
        int c = tid - 64;
        float q = 0.0f;
#pragma unroll
        for (int w = 0; w < 8; w++) q += s_sq[w * 64 + c];
        atomicAdd(&g_sumsq[slotoff + c], q);
    }
}

// ---------------- post: elementwise+learner for 64 nodes, then rb-GEMM to g_mh (fp16) ----------------
template <int MODE, int LAST>
__global__ void __launch_bounds__(256) k_post(int slotoff,
                                              const float* __restrict__ gam,
                                              const float* __restrict__ bet,
                                              const float* __restrict__ lw1,
                                              const float* __restrict__ lb1,
                                              const float* __restrict__ lw2,
                                              const float* __restrict__ lb2,
                                              const float* __restrict__ bwn) {
    __shared__ __align__(16) float Hs[64][66];   // [k][node]
    __shared__ __align__(16) float Ws[64][64];
    int tid = threadIdx.x;
    int lane = tid & 31, wid = tid >> 5;
    if (!LAST) {
        for (int i = tid; i < 1024; i += 256) {
            int k = i >> 4, c4 = i & 15;
            *((float4*)&Ws[k][c4 * 4]) = ((const float4*)(bwn + (size_t)k * 64))[c4];
        }
    }
    float scx = 1.0f, scy = 1.0f, shx = 0.0f, shy = 0.0f;
    if (MODE == 1) {
        const float ninv = 1.0f / (float)NN;
        float2 su = ((const float2*)(g_sum + slotoff))[lane];
        float2 sq = ((const float2*)(g_sumsq + slotoff))[lane];
        float2 gm = ((const float2*)gam)[lane];
        float2 bt = ((const float2*)bet)[lane];
        float mx = su.x * ninv, my = su.y * ninv;
        scx = gm.x * rsqrtf(sq.x * ninv - mx * mx + BNEPS);
        scy = gm.y * rsqrtf(sq.y * ninv - my * my + BNEPS);
        shx = bt.x - mx * scx;
        shy = bt.y - my * scy;
    }
#pragma unroll
    for (int n = 0; n < 8; n++) {
        int node = blockIdx.x * 64 + wid * 8 + n;
        float2 hv = make_float2(0.0f, 0.0f);
        if (node < NN) {
            float2 a = ((const float2*)(g_agg + (size_t)node * DD))[lane];
            float2 hn;
            if (MODE == 1) {
                hn.x = fmaxf(a.x * scx + shx, 0.0f);
                hn.y = fmaxf(a.y * scy + shy, 0.0f);
            } else {
                hn = a;
            }
            float2 fo = make_float2(0.0f, 0.0f);
            float2 d = hn;
            if (MODE == 1) {
                fo = ((const float2*)(g_fused + (size_t)node * DD))[lane];
                d.x = hn.x - fo.x;
                d.y = hn.y - fo.y;
            }
            float s = learner(d, lane, lw1, lb1, lw2, lb2);
            hv = make_float2(hn.x * s, hn.y * s);
            float2 fn = make_float2(fo.x + hv.x, fo.y + hv.y);
            ((float2*)(g_fused + (size_t)node * DD))[lane] = fn;
        }
        Hs[2 * lane][wid * 8 + n] = hv.x;
        Hs[2 * lane + 1][wid * 8 + n] = hv.y;
    }
    __syncthreads();
    if (LAST) return;
    // GEMM: m[64 nodes] = Hs^T @ Ws, stored fp16 to g_mh
    int tx = tid & 15, ty = tid >> 4;
    ull acc[2][4];
#pragma unroll
    for (int p = 0; p < 2; p++)
#pragma unroll
        for (int c = 0; c < 4; c++) acc[p][c] = 0ull;
#pragma unroll 8
    for (int k = 0; k < 64; k++) {
        ull a0 = *((const ull*)&Hs[k][ty * 4]);
        ull a1 = *((const ull*)&Hs[k][ty * 4 + 2]);
        float4 w = *((const float4*)&Ws[k][tx * 4]);
        ull wd[4];
        wd[0] = pack2(w.x, w.x); wd[1] = pack2(w.y, w.y);
        wd[2] = pack2(w.z, w.z); wd[3] = pack2(w.w, w.w);
#pragma unroll
        for (int c = 0; c < 4; c++) {
            FFMA2(acc[0][c], a0, wd[c], acc[0][c]);
            FFMA2(acc[1][c], a1, wd[c], acc[1][c]);
        }
    }
#pragma unroll
    for (int p = 0; p < 2; p++) {
        float2 c0 = unpack2(acc[p][0]), c1 = unpack2(acc[p][1]);
        float2 c2 = unpack2(acc[p][2]), c3 = unpack2(acc[p][3]);
        int gr0 = blockIdx.x * 64 + ty * 4 + 2 * p;
        if (gr0 < NN) {
            __half2 p0 = __floats2half2_rn(c0.x, c1.x);
            __half2 p1 = __floats2half2_rn(c2.x, c3.x);
            uint2 pk = make_uint2(*(unsigned*)&p0, *(unsigned*)&p1);
            *((uint2*)&g_mh[(size_t)gr0 * 32 + tx * 2]) = pk;
        }
        if (gr0 + 1 < NN) {
            __half2 p0 = __floats2half2_rn(c0.y, c1.y);
            __half2 p1 = __floats2half2_rn(c2.y, c3.y);
            uint2 pk = make_uint2(*(unsigned*)&p0, *(unsigned*)&p1);
            *((uint2*)&g_mh[(size_t)(gr0 + 1) * 32 + tx * 2]) = pk;
        }
    }
}

// ---------------- host orchestration ----------------
extern "C" void kernel_launch(void* const* d_in, const int* in_sizes, int n_in,
                              void* d_out, int out_size) {
    const float* x      = (const float*)d_in[0];
    const int*   ei     = (const int*)d_in[1];
    const float* im_w1  = (const float*)d_in[2];
    const float* im_b1  = (const float*)d_in[3];
    const float* im_g1  = (const float*)d_in[4];
    const float* im_be1 = (const float*)d_in[5];
    const float* im_w2  = (const float*)d_in[6];
    const float* im_b2  = (const float*)d_in[7];
    const float* lw1    = (const float*)d_in[8];
    const float* lb1    = (const float*)d_in[9];
    const float* lw2    = (const float*)d_in[10];
    const float* lb2    = (const float*)d_in[11];
    const float* bw     = (const float*)d_in[12];
    const float* bb     = (const float*)d_in[13];
    const float* bg     = (const float*)d_in[14];
    const float* bbe    = (const float*)d_in[15];
    const float* om_w1  = (const float*)d_in[16];
    const float* om_b1  = (const float*)d_in[17];
    const float* om_w2  = (const float*)d_in[18];
    const float* om_b2  = (const float*)d_in[19];
    float* outp = (float*)d_out;

    const int NB = (NN + 255) / 256;
    const int EB = (EE + 255) / 256;
    const int G128 = (NN + 127) / 128;  // 391 tiles
    const int G64 = (NN + 63) / 64;     // 782 blocks for k_post

    // 1-2: prep + degree count
    k_prep<<<NB, 256>>>();
    k_count<<<EB, 256>>>(ei);
    // 3-4: input-map GEMMs (slot 4 profiled)
    k_gemm<128, 0, 0, 1, -1, 0><<<G128, 256>>>(x, im_w1, 128, im_b1, nullptr, 128, 0, 0,
                                               nullptr, nullptr, 0);
    k_gemm<128, 0, 0, 1, -1, 0><<<G128, 256>>>(x, im_w1 + 64, 128, im_b1 + 64, nullptr, 128, 64, 64,
                                               nullptr, nullptr, 0);
    // 5-8: CSR build
    k_scanA<<<SCAN_B, 512>>>();
    k_scanB<<<1, 128>>>();
    k_scanC<<<SCAN_B, 512>>>();
    k_fill<<<EB, 256>>>(ei);
    // 9: input-map mid GEMM with fused BN+relu (g_t -> g_agg holds h)
    k_gemm<128, 1, 0, 0, 0, 2><<<G128, 256>>>(nullptr, im_w2, 64, im_b2, nullptr, 64, 0, 0,
                                              im_g1, im_be1, 0);
    // 10: learner0 + fused init + m = hv @ bw[0] (fp16)
    k_post<0, 0><<<G64, 256>>>(0, nullptr, nullptr, lw1, lb1, lw2, lb2, bw);
    // 11-26: 8 GCN blocks
    for (int li = 0; li < LL; li++) {
        k_gather<<<GW, 256>>>(bb + 64 * li, 128 + 64 * li);
        if (li < LL - 1) {
            k_post<1, 0><<<G64, 256>>>(128 + 64 * li, bg + 64 * li, bbe + 64 * li,
                                       lw1 + (size_t)(li + 1) * 256, lb1 + (li + 1) * 4,
                                       lw2 + (li + 1) * 4, lb2 + (li + 1),
                                       bw + (size_t)(li + 1) * 4096);
        } else {
            k_post<1, 1><<<G64, 256>>>(128 + 64 * li, bg + 64 * li, bbe + 64 * li,
                                       lw1 + (size_t)(li + 1) * 256, lb1 + (li + 1) * 4,
                                       lw2 + (li + 1) * 4, lb2 + (li + 1), nullptr);
        }
    }
    // 27-29: output map
    k_gemm<64, 0, 1, 0, 1, 0><<<G128, 256>>>(nullptr, om_w1, 128, om_b1, nullptr, 128, 0, 0,
                                             nullptr, nullptr, 0);
    k_gemm<64, 0, 1, 0, 1, 0><<<G128, 256>>>(nullptr, om_w1 + 64, 128, om_b1 + 64, nullptr, 128, 64, 0,
                                             nullptr, nullptr, 0);
    k_gemm<128, 0, 0, 0, 0, -1><<<G128, 256>>>(nullptr, om_w2, 64, om_b2, outp, 64, 0, 0,
                                               nullptr, nullptr, 0);
}

// round 16
// speedup vs baseline: 1.2247x; 1.1537x over previous
#include <cuda_runtime.h>
#include <cuda_fp16.h>
#include <math.h>

#define NN 50000
#define EE 800000
#define DD 64
#define FIN 128
#define LL 8
#define NSLOPE 0.2f
#define BNEPS 1e-5f
#define SCAN_B 98
#define NSTAT 640

typedef unsigned long long ull;

__device__ __forceinline__ ull pack2(float lo, float hi) {
    ull r; asm("mov.b64 %0, {%1,%2};" : "=l"(r) : "f"(lo), "f"(hi)); return r;
}
__device__ __forceinline__ float2 unpack2(ull v) {
    float2 f; asm("mov.b64 {%0,%1}, %2;" : "=f"(f.x), "=f"(f.y) : "l"(v)); return f;
}
#define FFMA2(d, a, b, c) \
    asm("fma.rn.f32x2 %0, %1, %2, %3;" : "=l"(d) : "l"(a), "l"(b), "l"(c))

// ---------------- scratch ----------------
__device__ float g_dinv[NN];
__device__ int   g_cnt[NN];
__device__ int   g_cursor[NN];
__device__ int   g_offs[NN + 1];
__device__ int   g_part[128];
__device__ int   g_partpref[128];
__device__ int2  g_csr[EE];
__device__ float g_t[(size_t)NN * FIN];
__device__ float g_fused[(size_t)NN * DD];
__device__ __half2 g_mh[(size_t)NN * 32];
__device__ float g_agg[(size_t)NN * DD];
__device__ float g_sum[NSTAT];
__device__ float g_sumsq[NSTAT];

__device__ __forceinline__ float* buf(int id) {
    switch (id) {
        case 0: return g_t;
        case 1: return g_fused;
        default: return g_agg;
    }
}

// ---------------- prep / CSR build ----------------
__global__ void k_prep() {
    int i = blockIdx.x * blockDim.x + threadIdx.x;
    if (i < NN) { g_cnt[i] = 0; g_cursor[i] = 0; }
    if (i < NSTAT) { g_sum[i] = 0.0f; g_sumsq[i] = 0.0f; }
}

__global__ void k_count(const int* __restrict__ ei) {
    int e = blockIdx.x * blockDim.x + threadIdx.x;
    if (e < EE) atomicAdd(&g_cnt[ei[EE + e]], 1);
}

__global__ void __launch_bounds__(512) k_scanA() {
    __shared__ int sh[512];
    int t = threadIdx.x;
    int i = blockIdx.x * 512 + t;
    sh[t] = (i < NN) ? g_cnt[i] : 0;
    __syncthreads();
    for (int off = 256; off >= 1; off >>= 1) {
        if (t < off) sh[t] += sh[t + off];
        __syncthreads();
    }
    if (t == 0) g_part[blockIdx.x] = sh[0];
}

__global__ void __launch_bounds__(128) k_scanB() {
    __shared__ int sh[128];
    int t = threadIdx.x;
    int v = (t < SCAN_B) ? g_part[t] : 0;
    sh[t] = v;
    __syncthreads();
    for (int off = 1; off < 128; off <<= 1) {
        int a = (t >= off) ? sh[t - off] : 0;
        __syncthreads();
        sh[t] += a;
        __syncthreads();
    }
    g_partpref[t] = sh[t] - v;
    if (t == SCAN_B - 1) g_offs[NN] = sh[t];
}

__global__ void __launch_bounds__(512) k_scanC() {
    __shared__ int sh[512];
    int t = threadIdx.x;
    int i = blockIdx.x * 512 + t;
    int v = (i < NN) ? g_cnt[i] : 0;
    sh[t] = v;
    __syncthreads();
    for (int off = 1; off < 512; off <<= 1) {
        int a = (t >= off) ? sh[t - off] : 0;
        __syncthreads();
        sh[t] += a;
        __syncthreads();
    }
    if (i < NN) {
        g_offs[i] = g_partpref[blockIdx.x] + sh[t] - v;
        g_dinv[i] = rsqrtf((float)(v + 1));
    }
}

__global__ void k_fill(const int* __restrict__ ei) {
    int e = blockIdx.x * blockDim.x + threadIdx.x;
    if (e < EE) {
        int s = ei[e];
        int v = ei[EE + e];
        int p = g_offs[v] + atomicAdd(&g_cursor[v], 1);
        g_csr[p] = make_int2(s, __float_as_int(g_dinv[s] * g_dinv[v]));
    }
}

// ---------------- learner ----------------
__device__ __forceinline__ float learner(float2 d, int lane,
                                         const float* __restrict__ w1,
                                         const float* __restrict__ b1,
                                         const float* __restrict__ w2,
                                         const float* __restrict__ b2) {
    float4 w1a = ((const float4*)w1)[2 * lane];
    float4 w1b = ((const float4*)w1)[2 * lane + 1];
    float4 p;
    p.x = d.x * w1a.x + d.y * w1b.x;
    p.y = d.x * w1a.y + d.y * w1b.y;
    p.z = d.x * w1a.z + d.y * w1b.z;
    p.w = d.x * w1a.w + d.y * w1b.w;
#pragma unroll
    for (int off = 16; off >= 1; off >>= 1) {
        p.x += __shfl_xor_sync(0xffffffffu, p.x, off);
        p.y += __shfl_xor_sync(0xffffffffu, p.y, off);
        p.z += __shfl_xor_sync(0xffffffffu, p.z, off);
        p.w += __shfl_xor_sync(0xffffffffu, p.w, off);
    }
    float4 bb1 = *((const float4*)b1);
    p.x += bb1.x; p.y += bb1.y; p.z += bb1.z; p.w += bb1.w;
    p.x = p.x > 0.0f ? p.x : NSLOPE * p.x;
    p.y = p.y > 0.0f ? p.y : NSLOPE * p.y;
    p.z = p.z > 0.0f ? p.z : NSLOPE * p.z;
    p.w = p.w > 0.0f ? p.w : NSLOPE * p.w;
    float4 ww2 = *((const float4*)w2);
    float z = p.x * ww2.x + p.y * ww2.y + p.z * ww2.z + p.w * ww2.w + b2[0];
    return 1.0f / (1.0f + __expf(-z));
}

// ---------------- N=64 GEMM (mid + final), 128x64 tile, f32x2 ----------------
template <int K, int PRE_BN, int ABUF, int OBUF>
__global__ void __launch_bounds__(256) k_gemm(const float* __restrict__ Aext,
                                              const float* __restrict__ W, int ldw,
                                              const float* __restrict__ bias,
                                              float* __restrict__ Oext, int ldo,
                                              const float* __restrict__ gam,
                                              const float* __restrict__ bet, int bnslot) {
    const float* A = (ABUF < 0) ? Aext : buf(ABUF);
    float* O = (OBUF < 0) ? Oext : buf(OBUF);
    __shared__ __align__(16) float As[32][130];
    __shared__ __align__(16) float Ws[32][64];
    __shared__ float SC[FIN], SH[FIN];
    int tid = threadIdx.x;
    int tx = tid & 15, ty = tid >> 4;
    int row0 = blockIdx.x * 128;

    if (PRE_BN) {
        if (tid < K) {
            const float ninv = 1.0f / (float)NN;
            float mean = g_sum[bnslot + tid] * ninv;
            float var = g_sumsq[bnslot + tid] * ninv - mean * mean;
            float sc = gam[tid] * rsqrtf(var + BNEPS);
            SC[tid] = sc;
            SH[tid] = bet[tid] - mean * sc;
        }
        __syncthreads();
    }

    float4 bv = ((const float4*)bias)[tx];
    ull acc[4][4];
#pragma unroll
    for (int p = 0; p < 4; p++) {
        acc[p][0] = pack2(bv.x, bv.x);
        acc[p][1] = pack2(bv.y, bv.y);
        acc[p][2] = pack2(bv.z, bv.z);
        acc[p][3] = pack2(bv.w, bv.w);
    }

#pragma unroll
    for (int kc = 0; kc < K / 32; kc++) {
        if (kc > 0) __syncthreads();
        for (int i = tid; i < 1024; i += 256) {
            int r = i >> 3, c4 = i & 7;
            int gr = row0 + r; if (gr >= NN) gr = NN - 1;
            float4 v = ((const float4*)(A + (size_t)gr * K + kc * 32))[c4];
            if (PRE_BN) {
                int c = kc * 32 + c4 * 4;
                v.x = fmaxf(v.x * SC[c] + SH[c], 0.0f);
                v.y = fmaxf(v.y * SC[c + 1] + SH[c + 1], 0.0f);
                v.z = fmaxf(v.z * SC[c + 2] + SH[c + 2], 0.0f);
                v.w = fmaxf(v.w * SC[c + 3] + SH[c + 3], 0.0f);
            }
            As[4 * c4 + 0][r] = v.x;
            As[4 * c4 + 1][r] = v.y;
            As[4 * c4 + 2][r] = v.z;
            As[4 * c4 + 3][r] = v.w;
        }
        for (int i = tid; i < 512; i += 256) {
            int k = i >> 4, c4 = i & 15;
            float4 v = ((const float4*)(W + (size_t)(kc * 32 + k) * ldw))[c4];
            *((float4*)&Ws[k][c4 * 4]) = v;
        }
        __syncthreads();
#pragma unroll 8
        for (int k = 0; k < 32; k++) {
            ull a[4];
#pragma unroll
            for (int p = 0; p < 4; p++)
                a[p] = *((const ull*)&As[k][ty * 8 + 2 * p]);
            float4 w = *((const float4*)&Ws[k][tx * 4]);
            ull wd[4];
            wd[0] = pack2(w.x, w.x); wd[1] = pack2(w.y, w.y);
            wd[2] = pack2(w.z, w.z); wd[3] = pack2(w.w, w.w);
#pragma unroll
            for (int p = 0; p < 4; p++)
#pragma unroll
                for (int c = 0; c < 4; c++)
                    FFMA2(acc[p][c], a[p], wd[c], acc[p][c]);
        }
    }

#pragma unroll
    for (int p = 0; p < 4; p++) {
        float2 c0 = unpack2(acc[p][0]), c1 = unpack2(acc[p][1]);
        float2 c2 = unpack2(acc[p][2]), c3 = unpack2(acc[p][3]);
        int gr0 = row0 + ty * 8 + 2 * p;
        if (gr0 < NN)
            *((float4*)(O + (size_t)gr0 * ldo + tx * 4)) = make_float4(c0.x, c1.x, c2.x, c3.x);
        if (gr0 + 1 < NN)
            *((float4*)(O + (size_t)(gr0 + 1) * ldo + tx * 4)) = make_float4(c0.y, c1.y, c2.y, c3.y);
    }
}

// ---------------- N=128 GEMM (merged input / output-1): 64x128 tile, dual-Ws ----------------
template <int K, int POST_RELU, int STATS, int ABUF>
__global__ void __launch_bounds__(256) k_gemmW(const float* __restrict__ Aext,
                                               const float* __restrict__ W,
                                               const float* __restrict__ bias,
                                               int slotoff) {
    const float* A = (ABUF < 0) ? Aext : buf(ABUF);
    float* O = g_t;
    __shared__ __align__(16) float As[32][66];
    __shared__ __align__(16) float Wa[32][64];
    __shared__ __align__(16) float Wb[32][64];
    __shared__ __align__(16) float Ssum[16][128];
    __shared__ __align__(16) float Ssq[16][128];
    int tid = threadIdx.x;
    int tx = tid & 15, ty = tid >> 4;
    int row0 = blockIdx.x * 64;

    float4 ba = ((const float4*)bias)[tx];
    float4 bbv = ((const float4*)bias)[16 + tx];
    ull acc[2][8];
#pragma unroll
    for (int p = 0; p < 2; p++) {
        acc[p][0] = pack2(ba.x, ba.x); acc[p][1] = pack2(ba.y, ba.y);
        acc[p][2] = pack2(ba.z, ba.z); acc[p][3] = pack2(ba.w, ba.w);
        acc[p][4] = pack2(bbv.x, bbv.x); acc[p][5] = pack2(bbv.y, bbv.y);
        acc[p][6] = pack2(bbv.z, bbv.z); acc[p][7] = pack2(bbv.w, bbv.w);
    }

#pragma unroll
    for (int kc = 0; kc < K / 32; kc++) {
        if (kc > 0) __syncthreads();
        // stage A: 64 rows x 32 k (512 float4)
        for (int i = tid; i < 512; i += 256) {
            int r = i >> 3, c4 = i & 7;
            int gr = row0 + r; if (gr >= NN) gr = NN - 1;
            float4 v = ((const float4*)(A + (size_t)gr * K + kc * 32))[c4];
            As[4 * c4 + 0][r] = v.x;
            As[4 * c4 + 1][r] = v.y;
            As[4 * c4 + 2][r] = v.z;
            As[4 * c4 + 3][r] = v.w;
        }
        // stage W: 32 k x 128 cols split into Wa (cols 0..63) + Wb (64..127)
        for (int i = tid; i < 1024; i += 256) {
            int k = i >> 5, q = i & 31;
            float4 v = ((const float4*)(W + (size_t)(kc * 32 + k) * 128))[q];
            if (q < 16) *((float4*)&Wa[k][q * 4]) = v;
            else        *((float4*)&Wb[k][(q - 16) * 4]) = v;
        }
        __syncthreads();
#pragma unroll 8
        for (int k = 0; k < 32; k++) {
            ull a0 = *((const ull*)&As[k][ty * 4]);
            ull a1 = *((const ull*)&As[k][ty * 4 + 2]);
            float4 wa = *((const float4*)&Wa[k][tx * 4]);
            float4 wb = *((const float4*)&Wb[k][tx * 4]);
            ull wd[8];
            wd[0] = pack2(wa.x, wa.x); wd[1] = pack2(wa.y, wa.y);
            wd[2] = pack2(wa.z, wa.z); wd[3] = pack2(wa.w, wa.w);
            wd[4] = pack2(wb.x, wb.x); wd[5] = pack2(wb.y, wb.y);
            wd[6] = pack2(wb.z, wb.z); wd[7] = pack2(wb.w, wb.w);
#pragma unroll
            for (int c = 0; c < 8; c++) {
                FFMA2(acc[0][c], a0, wd[c], acc[0][c]);
                FFMA2(acc[1][c], a1, wd[c], acc[1][c]);
            }
        }
    }

    float ps[8], pq[8];
#pragma unroll
    for (int c = 0; c < 8; c++) { ps[c] = 0.0f; pq[c] = 0.0f; }
#pragma unroll
    for (int p = 0; p < 2; p++) {
        float2 cc[8];
#pragma unroll
        for (int c = 0; c < 8; c++) {
            cc[c] = unpack2(acc[p][c]);
            if (POST_RELU) { cc[c].x = fmaxf(cc[c].x, 0.0f); cc[c].y = fmaxf(cc[c].y, 0.0f); }
        }
        int gr0 = row0 + ty * 4 + 2 * p;
        if (gr0 < NN) {
            *((float4*)(O + (size_t)gr0 * FIN + tx * 4)) = make_float4(cc[0].x, cc[1].x, cc[2].x, cc[3].x);
            *((float4*)(O + (size_t)gr0 * FIN + 64 + tx * 4)) = make_float4(cc[4].x, cc[5].x, cc[6].x, cc[7].x);
            if (STATS)
#pragma unroll
                for (int c = 0; c < 8; c++) { ps[c] += cc[c].x; pq[c] += cc[c].x * cc[c].x; }
        }
        if (gr0 + 1 < NN) {
            *((float4*)(O + (size_t)(gr0 + 1) * FIN + tx * 4)) = make_float4(cc[0].y, cc[1].y, cc[2].y, cc[3].y);
            *((float4*)(O + (size_t)(gr0 + 1) * FIN + 64 + tx * 4)) = make_float4(cc[4].y, cc[5].y, cc[6].y, cc[7].y);
            if (STATS)
#pragma unroll
                for (int c = 0; c < 8; c++) { ps[c] += cc[c].y; pq[c] += cc[c].y * cc[c].y; }
        }
    }
    if (STATS) {
        __syncthreads();
        *((float4*)&Ssum[ty][tx * 4]) = make_float4(ps[0], ps[1], ps[2], ps[3]);
        *((float4*)&Ssum[ty][64 + tx * 4]) = make_float4(ps[4], ps[5], ps[6], ps[7]);
        *((float4*)&Ssq[ty][tx * 4]) = make_float4(pq[0], pq[1], pq[2], pq[3]);
        *((float4*)&Ssq[ty][64 + tx * 4]) = make_float4(pq[4], pq[5], pq[6], pq[7]);
        __syncthreads();
        if (tid < 128) {
            float s = 0.0f;
#pragma unroll
            for (int t = 0; t < 16; t++) s += Ssum[t][tid];
            atomicAdd(&g_sum[slotoff + tid], s);
        } else {
            int c = tid - 128;
            float q = 0.0f;
#pragma unroll
            for (int t = 0; t < 16; t++) q += Ssq[t][c];
            atomicAdd(&g_sumsq[slotoff + c], q);
        }
    }
}

// ---------------- gather v2: 2 nodes/warp (half-warp rows), fused stats ----------------
// 256 threads = 8 warps = 16 nodes/block; grid 3125 (exact).
__global__ void __launch_bounds__(256) k_gather(const float* __restrict__ bbL, int slotoff) {
    int tid = threadIdx.x;
    int lane = tid & 31, wid = tid >> 5;
    int half = lane >> 4, hl = lane & 15;
    int nib = wid * 2 + half;
    int v = blockIdx.x * 16 + nib;
    float dv = g_dinv[v];
    float ws = dv * dv;
    // self row: lane covers cols hl*4 .. hl*4+3
    uint2 mv2 = *((const uint2*)&g_mh[(size_t)v * 32 + hl * 2]);
    float2 f0 = __half22float2(*(__half2*)&mv2.x);
    float2 f1 = __half22float2(*(__half2*)&mv2.y);
    float4 acc = make_float4(f0.x * ws, f0.y * ws, f1.x * ws, f1.y * ws);
    int beg = g_offs[v], end = g_offs[v + 1];
    int deg = end - beg;
    int md = max(deg, __shfl_xor_sync(0xffffffffu, deg, 16));
    for (int jj = 0; jj < md; jj += 16) {
        int j = beg + jj;
        int2 e = (j + hl < end) ? g_csr[j + hl] : make_int2(0, 0);
#pragma unroll
        for (int u = 0; u < 16; u++) {
            int idx = __shfl_sync(0xffffffffu, e.x, u, 16);
            float w = __int_as_float(__shfl_sync(0xffffffffu, e.y, u, 16));
            uint2 r = *((const uint2*)&g_mh[(size_t)idx * 32 + hl * 2]);
            float2 a = __half22float2(*(__half2*)&r.x);
            float2 b = __half22float2(*(__half2*)&r.y);
            acc.x = fmaf(w, a.x, acc.x);
            acc.y = fmaf(w, a.y, acc.y);
            acc.z = fmaf(w, b.x, acc.z);
            acc.w = fmaf(w, b.y, acc.w);
        }
    }
    float4 b4 = ((const float4*)bbL)[hl];
    acc.x += b4.x; acc.y += b4.y; acc.z += b4.z; acc.w += b4.w;
    *((float4*)(g_agg + (size_t)v * DD + hl * 4)) = acc;
    __shared__ __align__(16) float s_sum[16][64], s_sq[16][64];
    *((float4*)&s_sum[nib][hl * 4]) = acc;
    *((float4*)&s_sq[nib][hl * 4]) =
        make_float4(acc.x * acc.x, acc.y * acc.y, acc.z * acc.z, acc.w * acc.w);
    __syncthreads();
    if (tid < 64) {
        float s = 0.0f;
#pragma unroll
        for (int r = 0; r < 16; r++) s += s_sum[r][tid];
        atomicAdd(&g_sum[slotoff + tid], s);
    } else if (tid < 128) {
        int c = tid - 64;
        float q = 0.0f;
#pragma unroll
        for (int r = 0; r < 16; r++) q += s_sq[r][c];
        atomicAdd(&g_sumsq[slotoff + c], q);
    }
}

// ---------------- post: elementwise+learner for 64 nodes, then rb-GEMM to g_mh (fp16) ----------------
template <int MODE, int LAST>
__global__ void __launch_bounds__(256) k_post(int slotoff,
                                              const float* __restrict__ gam,
                                              const float* __restrict__ bet,
                                              const float* __restrict__ lw1,
                                              const float* __restrict__ lb1,
                                              const float* __restrict__ lw2,
                                              const float* __restrict__ lb2,
                                              const float* __restrict__ bwn) {
    __shared__ __align__(16) float Hs[64][66];
    __shared__ __align__(16) float Ws[64][64];
    int tid = threadIdx.x;
    int lane = tid & 31, wid = tid >> 5;
    if (!LAST) {
        for (int i = tid; i < 1024; i += 256) {
            int k = i >> 4, c4 = i & 15;
            *((float4*)&Ws[k][c4 * 4]) = ((const float4*)(bwn + (size_t)k * 64))[c4];
        }
    }
    float scx = 1.0f, scy = 1.0f, shx = 0.0f, shy = 0.0f;
    if (MODE == 1) {
        const float ninv = 1.0f / (float)NN;
        float2 su = ((const float2*)(g_sum + slotoff))[lane];
        float2 sq = ((const float2*)(g_sumsq + slotoff))[lane];
        float2 gm = ((const float2*)gam)[lane];
        float2 bt = ((const float2*)bet)[lane];
        float mx = su.x * ninv, my = su.y * ninv;
        scx = gm.x * rsqrtf(sq.x * ninv - mx * mx + BNEPS);
        scy = gm.y * rsqrtf(sq.y * ninv - my * my + BNEPS);
        shx = bt.x - mx * scx;
        shy = bt.y - my * scy;
    }
#pragma unroll
    for (int n = 0; n < 8; n++) {
        int node = blockIdx.x * 64 + wid * 8 + n;
        float2 hv = make_float2(0.0f, 0.0f);
        if (node < NN) {
            float2 a = ((const float2*)(g_agg + (size_t)node * DD))[lane];
            float2 hn;
            if (MODE == 1) {
                hn.x = fmaxf(a.x * scx + shx, 0.0f);
                hn.y = fmaxf(a.y * scy + shy, 0.0f);
            } else {
                hn = a;
            }
            float2 fo = make_float2(0.0f, 0.0f);
            float2 d = hn;
            if (MODE == 1) {
                fo = ((const float2*)(g_fused + (size_t)node * DD))[lane];
                d.x = hn.x - fo.x;
                d.y = hn.y - fo.y;
            }
            float s = learner(d, lane, lw1, lb1, lw2, lb2);
            hv = make_float2(hn.x * s, hn.y * s);
            float2 fn = make_float2(fo.x + hv.x, fo.y + hv.y);
            ((float2*)(g_fused + (size_t)node * DD))[lane] = fn;
        }
        Hs[2 * lane][wid * 8 + n] = hv.x;
        Hs[2 * lane + 1][wid * 8 + n] = hv.y;
    }
    __syncthreads();
    if (LAST) return;
    int tx = tid & 15, ty = tid >> 4;
    ull acc[2][4];
#pragma unroll
    for (int p = 0; p < 2; p++)
#pragma unroll
        for (int c = 0; c < 4; c++) acc[p][c] = 0ull;
#pragma unroll 8
    for (int k = 0; k < 64; k++) {
        ull a0 = *((const ull*)&Hs[k][ty * 4]);
        ull a1 = *((const ull*)&Hs[k][ty * 4 + 2]);
        float4 w = *((const float4*)&Ws[k][tx * 4]);
        ull wd[4];
        wd[0] = pack2(w.x, w.x); wd[1] = pack2(w.y, w.y);
        wd[2] = pack2(w.z, w.z); wd[3] = pack2(w.w, w.w);
#pragma unroll
        for (int c = 0; c < 4; c++) {
            FFMA2(acc[0][c], a0, wd[c], acc[0][c]);
            FFMA2(acc[1][c], a1, wd[c], acc[1][c]);
        }
    }
#pragma unroll
    for (int p = 0; p < 2; p++) {
        float2 c0 = unpack2(acc[p][0]), c1 = unpack2(acc[p][1]);
        float2 c2 = unpack2(acc[p][2]), c3 = unpack2(acc[p][3]);
        int gr0 = blockIdx.x * 64 + ty * 4 + 2 * p;
        if (gr0 < NN) {
            __half2 p0 = __floats2half2_rn(c0.x, c1.x);
            __half2 p1 = __floats2half2_rn(c2.x, c3.x);
            uint2 pk = make_uint2(*(unsigned*)&p0, *(unsigned*)&p1);
            *((uint2*)&g_mh[(size_t)gr0 * 32 + tx * 2]) = pk;
        }
        if (gr0 + 1 < NN) {
            __half2 p0 = __floats2half2_rn(c0.y, c1.y);
            __half2 p1 = __floats2half2_rn(c2.y, c3.y);
            uint2 pk = make_uint2(*(unsigned*)&p0, *(unsigned*)&p1);
            *((uint2*)&g_mh[(size_t)(gr0 + 1) * 32 + tx * 2]) = pk;
        }
    }
}

// ---------------- host orchestration ----------------
extern "C" void kernel_launch(void* const* d_in, const int* in_sizes, int n_in,
                              void* d_out, int out_size) {
    const float* x      = (const float*)d_in[0];
    const int*   ei     = (const int*)d_in[1];
    const float* im_w1  = (const float*)d_in[2];
    const float* im_b1  = (const float*)d_in[3];
    const float* im_g1  = (const float*)d_in[4];
    const float* im_be1 = (const float*)d_in[5];
    const float* im_w2  = (const float*)d_in[6];
    const float* im_b2  = (const float*)d_in[7];
    const float* lw1    = (const float*)d_in[8];
    const float* lb1    = (const float*)d_in[9];
    const float* lw2    = (const float*)d_in[10];
    const float* lb2    = (const float*)d_in[11];
    const float* bw     = (const float*)d_in[12];
    const float* bb     = (const float*)d_in[13];
    const float* bg     = (const float*)d_in[14];
    const float* bbe    = (const float*)d_in[15];
    const float* om_w1  = (const float*)d_in[16];
    const float* om_b1  = (const float*)d_in[17];
    const float* om_w2  = (const float*)d_in[18];
    const float* om_b2  = (const float*)d_in[19];
    float* outp = (float*)d_out;

    const int NB = (NN + 255) / 256;
    const int EB = (EE + 255) / 256;
    const int G128 = (NN + 127) / 128;  // 391
    const int G64 = (NN + 63) / 64;     // 782
    const int GG = NN / 16;             // 3125 gather blocks

    // 1-3
    k_prep<<<NB, 256>>>();
    k_count<<<EB, 256>>>(ei);
    k_scanA<<<SCAN_B, 512>>>();
    // 4: merged input-map GEMM (profiled slot)
    k_gemmW<128, 0, 1, -1><<<G64, 256>>>(x, im_w1, im_b1, 0);
    // 5-7
    k_scanB<<<1, 128>>>();
    k_scanC<<<SCAN_B, 512>>>();
    k_fill<<<EB, 256>>>(ei);
    // 8: mid GEMM with fused BN+relu (g_t -> g_agg)
    k_gemm<128, 1, 0, 2><<<G128, 256>>>(nullptr, im_w2, 64, im_b2, nullptr, 64,
                                        im_g1, im_be1, 0);
    // 9: learner0 + fused init + m (fp16)
    k_post<0, 0><<<G64, 256>>>(0, nullptr, nullptr, lw1, lb1, lw2, lb2, bw);
    // 10-25: 8 GCN blocks
    for (int li = 0; li < LL; li++) {
        k_gather<<<GG, 256>>>(bb + 64 * li, 128 + 64 * li);
        if (li < LL - 1) {
            k_post<1, 0><<<G64, 256>>>(128 + 64 * li, bg + 64 * li, bbe + 64 * li,
                                       lw1 + (size_t)(li + 1) * 256, lb1 + (li + 1) * 4,
                                       lw2 + (li + 1) * 4, lb2 + (li + 1),
                                       bw + (size_t)(li + 1) * 4096);
        } else {
            k_post<1, 1><<<G64, 256>>>(128 + 64 * li, bg + 64 * li, bbe + 64 * li,
                                       lw1 + (size_t)(li + 1) * 256, lb1 + (li + 1) * 4,
                                       lw2 + (li + 1) * 4, lb2 + (li + 1), nullptr);
        }
    }
    // 26: merged output GEMM 1 (fused -> g_t, relu)
    k_gemmW<64, 1, 0, 1><<<G64, 256>>>(nullptr, om_w1, om_b1, 0);
    // 27: final GEMM (g_t -> out)
    k_gemm<128, 0, 0, -1><<<G128, 256>>>(nullptr, om_w2, 64, om_b2, outp, 64,
                                         nullptr, nullptr, 0);
}

// round 17
// speedup vs baseline: 1.2726x; 1.0391x over previous
#include <cuda_runtime.h>
#include <cuda_fp16.h>
#include <math.h>

#define NN 50000
#define EE 800000
#define DD 64
#define FIN 128
#define LL 8
#define NSLOPE 0.2f
#define BNEPS 1e-5f
#define SCAN_B 98
#define NSTAT 640

typedef unsigned long long ull;

__device__ __forceinline__ ull pack2(float lo, float hi) {
    ull r; asm("mov.b64 %0, {%1,%2};" : "=l"(r) : "f"(lo), "f"(hi)); return r;
}
__device__ __forceinline__ float2 unpack2(ull v) {
    float2 f; asm("mov.b64 {%0,%1}, %2;" : "=f"(f.x), "=f"(f.y) : "l"(v)); return f;
}
#define FFMA2(d, a, b, c) \
    asm("fma.rn.f32x2 %0, %1, %2, %3;" : "=l"(d) : "l"(a), "l"(b), "l"(c))

// ---------------- scratch ----------------
__device__ float g_dinv[NN];
__device__ int   g_cnt[NN];
__device__ int   g_cursor[NN];
__device__ int   g_offs[NN + 1];
__device__ int   g_part[128];
__device__ int2  g_csr[EE];
__device__ float g_t[(size_t)NN * FIN];
__device__ float g_fused[(size_t)NN * DD];
__device__ __half2 g_mh[(size_t)NN * 32];
__device__ float g_agg[(size_t)NN * DD];
__device__ float g_sum[NSTAT];
__device__ float g_sumsq[NSTAT];

__device__ __forceinline__ float* buf(int id) {
    switch (id) {
        case 0: return g_t;
        case 1: return g_fused;
        default: return g_agg;
    }
}

// ---------------- prep / CSR build ----------------
__global__ void k_prep() {
    int i = blockIdx.x * blockDim.x + threadIdx.x;
    if (i < NN) { g_cnt[i] = 0; }
    if (i < NSTAT) { g_sum[i] = 0.0f; g_sumsq[i] = 0.0f; }
}

__global__ void k_count(const int* __restrict__ ei) {
    int e = blockIdx.x * blockDim.x + threadIdx.x;
    if (e < EE) atomicAdd(&g_cnt[ei[EE + e]], 1);
}

__global__ void __launch_bounds__(512) k_scanA() {
    __shared__ int sh[512];
    int t = threadIdx.x;
    int i = blockIdx.x * 512 + t;
    sh[t] = (i < NN) ? g_cnt[i] : 0;
    __syncthreads();
    for (int off = 256; off >= 1; off >>= 1) {
        if (t < off) sh[t] += sh[t + off];
        __syncthreads();
    }
    if (t == 0) g_part[blockIdx.x] = sh[0];
}

// scanC now also re-scans the 98 partials locally (scanB folded in)
__global__ void __launch_bounds__(512) k_scanC() {
    __shared__ int sh[512];
    __shared__ int pp[128];
    int t = threadIdx.x;
    if (t < 128) pp[t] = (t < SCAN_B) ? g_part[t] : 0;
    __syncthreads();
    for (int off = 1; off < 128; off <<= 1) {
        int a = (t < 128 && t >= off) ? pp[t - off] : 0;
        __syncthreads();
        if (t < 128) pp[t] += a;
        __syncthreads();
    }
    int i = blockIdx.x * 512 + t;
    int v = (i < NN) ? g_cnt[i] : 0;
    sh[t] = v;
    __syncthreads();
    for (int off = 1; off < 512; off <<= 1) {
        int a = (t >= off) ? sh[t - off] : 0;
        __syncthreads();
        sh[t] += a;
        __syncthreads();
    }
    int base = pp[blockIdx.x] - g_part[blockIdx.x];  // exclusive block prefix
    if (i < NN) {
        g_offs[i] = base + sh[t] - v;
        g_dinv[i] = rsqrtf((float)(v + 1));
        g_cnt[i] = 0;  // reuse as cursor for k_fill
    }
    if (i == NN - 1) g_offs[NN] = base + sh[t];
}

__global__ void k_fill(const int* __restrict__ ei) {
    int e = blockIdx.x * blockDim.x + threadIdx.x;
    if (e < EE) {
        int s = ei[e];
        int v = ei[EE + e];
        int p = g_offs[v] + atomicAdd(&g_cnt[v], 1);
        g_csr[p] = make_int2(s, __float_as_int(g_dinv[s] * g_dinv[v]));
    }
}

// ---------------- learner ----------------
__device__ __forceinline__ float learner(float2 d, int lane,
                                         const float* __restrict__ w1,
                                         const float* __restrict__ b1,
                                         const float* __restrict__ w2,
                                         const float* __restrict__ b2) {
    float4 w1a = ((const float4*)w1)[2 * lane];
    float4 w1b = ((const float4*)w1)[2 * lane + 1];
    float4 p;
    p.x = d.x * w1a.x + d.y * w1b.x;
    p.y = d.x * w1a.y + d.y * w1b.y;
    p.z = d.x * w1a.z + d.y * w1b.z;
    p.w = d.x * w1a.w + d.y * w1b.w;
#pragma unroll
    for (int off = 16; off >= 1; off >>= 1) {
        p.x += __shfl_xor_sync(0xffffffffu, p.x, off);
        p.y += __shfl_xor_sync(0xffffffffu, p.y, off);
        p.z += __shfl_xor_sync(0xffffffffu, p.z, off);
        p.w += __shfl_xor_sync(0xffffffffu, p.w, off);
    }
    float4 bb1 = *((const float4*)b1);
    p.x += bb1.x; p.y += bb1.y; p.z += bb1.z; p.w += bb1.w;
    p.x = p.x > 0.0f ? p.x : NSLOPE * p.x;
    p.y = p.y > 0.0f ? p.y : NSLOPE * p.y;
    p.z = p.z > 0.0f ? p.z : NSLOPE * p.z;
    p.w = p.w > 0.0f ? p.w : NSLOPE * p.w;
    float4 ww2 = *((const float4*)w2);
    float z = p.x * ww2.x + p.y * ww2.y + p.z * ww2.z + p.w * ww2.w + b2[0];
    return 1.0f / (1.0f + __expf(-z));
}

// ---------------- N=64 GEMM (mid + final): 128x64 tile, double-buffered K-chunk 16 ----------------
template <int K, int PRE_BN, int ABUF, int OBUF>
__global__ void __launch_bounds__(256) k_gemm(const float* __restrict__ Aext,
                                              const float* __restrict__ W, int ldw,
                                              const float* __restrict__ bias,
                                              float* __restrict__ Oext, int ldo,
                                              const float* __restrict__ gam,
                                              const float* __restrict__ bet, int bnslot) {
    const float* A = (ABUF < 0) ? Aext : buf(ABUF);
    float* O = (OBUF < 0) ? Oext : buf(OBUF);
    __shared__ __align__(16) float As[2][16][130];
    __shared__ __align__(16) float Ws[2][16][64];
    __shared__ float SC[FIN], SH[FIN];
    int tid = threadIdx.x;
    int tx = tid & 15, ty = tid >> 4;
    int row0 = blockIdx.x * 128;
    const int NC = K / 16;

    if (PRE_BN) {
        if (tid < K) {
            const float ninv = 1.0f / (float)NN;
            float mean = g_sum[bnslot + tid] * ninv;
            float var = g_sumsq[bnslot + tid] * ninv - mean * mean;
            float sc = gam[tid] * rsqrtf(var + BNEPS);
            SC[tid] = sc;
            SH[tid] = bet[tid] - mean * sc;
        }
        __syncthreads();
    }

#define STAGE_G(kc, b)                                                           \
    {                                                                            \
        _Pragma("unroll")                                                        \
        for (int tt = 0; tt < 2; tt++) {                                         \
            int i = tid + 256 * tt;                                              \
            int r = i >> 2, c4 = i & 3;                                          \
            int gr = row0 + r; if (gr >= NN) gr = NN - 1;                        \
            float4 v = ((const float4*)(A + (size_t)gr * K + (kc) * 16))[c4];    \
            if (PRE_BN) {                                                        \
                int c = (kc) * 16 + c4 * 4;                                      \
                v.x = fmaxf(v.x * SC[c] + SH[c], 0.0f);                          \
                v.y = fmaxf(v.y * SC[c + 1] + SH[c + 1], 0.0f);                  \
                v.z = fmaxf(v.z * SC[c + 2] + SH[c + 2], 0.0f);                  \
                v.w = fmaxf(v.w * SC[c + 3] + SH[c + 3], 0.0f);                  \
            }                                                                    \
            As[b][4 * c4 + 0][r] = v.x;                                          \
            As[b][4 * c4 + 1][r] = v.y;                                          \
            As[b][4 * c4 + 2][r] = v.z;                                          \
            As[b][4 * c4 + 3][r] = v.w;                                          \
        }                                                                        \
        {                                                                        \
            int k = tid >> 4, c4 = tid & 15;                                     \
            float4 v = ((const float4*)(W + (size_t)((kc) * 16 + k) * ldw))[c4]; \
            *((float4*)&Ws[b][k][c4 * 4]) = v;                                   \
        }                                                                        \
    }

    float4 bv = ((const float4*)bias)[tx];
    ull acc[4][4];
#pragma unroll
    for (int p = 0; p < 4; p++) {
        acc[p][0] = pack2(bv.x, bv.x);
        acc[p][1] = pack2(bv.y, bv.y);
        acc[p][2] = pack2(bv.z, bv.z);
        acc[p][3] = pack2(bv.w, bv.w);
    }

    STAGE_G(0, 0);
    __syncthreads();
#pragma unroll
    for (int kc = 0; kc < NC; kc++) {
        if (kc + 1 < NC) STAGE_G(kc + 1, (kc + 1) & 1);
        int b = kc & 1;
#pragma unroll
        for (int k = 0; k < 16; k++) {
            ull a[4];
#pragma unroll
            for (int p = 0; p < 4; p++)
                a[p] = *((const ull*)&As[b][k][ty * 8 + 2 * p]);
            float4 w = *((const float4*)&Ws[b][k][tx * 4]);
            ull wd[4];
            wd[0] = pack2(w.x, w.x); wd[1] = pack2(w.y, w.y);
            wd[2] = pack2(w.z, w.z); wd[3] = pack2(w.w, w.w);
#pragma unroll
            for (int p = 0; p < 4; p++)
#pragma unroll
                for (int c = 0; c < 4; c++)
                    FFMA2(acc[p][c], a[p], wd[c], acc[p][c]);
        }
        __syncthreads();
    }
#undef STAGE_G

#pragma unroll
    for (int p = 0; p < 4; p++) {
        float2 c0 = unpack2(acc[p][0]), c1 = unpack2(acc[p][1]);
        float2 c2 = unpack2(acc[p][2]), c3 = unpack2(acc[p][3]);
        int gr0 = row0 + ty * 8 + 2 * p;
        if (gr0 < NN)
            *((float4*)(O + (size_t)gr0 * ldo + tx * 4)) = make_float4(c0.x, c1.x, c2.x, c3.x);
        if (gr0 + 1 < NN)
            *((float4*)(O + (size_t)(gr0 + 1) * ldo + tx * 4)) = make_float4(c0.y, c1.y, c2.y, c3.y);
    }
}

// ---------------- N=128 GEMM (merged input / output-1): 64x128, double-buffered ----------------
template <int K, int POST_RELU, int STATS, int ABUF>
__global__ void __launch_bounds__(256) k_gemmW(const float* __restrict__ Aext,
                                               const float* __restrict__ W,
                                               const float* __restrict__ bias,
                                               int slotoff) {
    const float* A = (ABUF < 0) ? Aext : buf(ABUF);
    float* O = g_t;
    __shared__ __align__(16) float As[2][16][66];
    __shared__ __align__(16) float Wa[2][16][64];
    __shared__ __align__(16) float Wb[2][16][64];
    __shared__ __align__(16) float Ssum[16][128];
    __shared__ __align__(16) float Ssq[16][128];
    int tid = threadIdx.x;
    int tx = tid & 15, ty = tid >> 4;
    int row0 = blockIdx.x * 64;
    const int NC = K / 16;

#define STAGE_W(kc, b)                                                            \
    {                                                                             \
        {                                                                         \
            int r = tid >> 2, c4 = tid & 3;                                       \
            int gr = row0 + r; if (gr >= NN) gr = NN - 1;                         \
            float4 v = ((const float4*)(A + (size_t)gr * K + (kc) * 16))[c4];     \
            As[b][4 * c4 + 0][r] = v.x;                                           \
            As[b][4 * c4 + 1][r] = v.y;                                           \
            As[b][4 * c4 + 2][r] = v.z;                                           \
            As[b][4 * c4 + 3][r] = v.w;                                           \
        }                                                                         \
        _Pragma("unroll")                                                         \
        for (int tt = 0; tt < 2; tt++) {                                          \
            int i = tid + 256 * tt;                                               \
            int k = i >> 5, q = i & 31;                                           \
            float4 v = ((const float4*)(W + (size_t)((kc) * 16 + k) * 128))[q];   \
            if (q < 16) *((float4*)&Wa[b][k][q * 4]) = v;                         \
            else        *((float4*)&Wb[b][k][(q - 16) * 4]) = v;                  \
        }                                                                         \
    }

    float4 ba = ((const float4*)bias)[tx];
    float4 bbv = ((const float4*)bias)[16 + tx];
    ull acc[2][8];
#pragma unroll
    for (int p = 0; p < 2; p++) {
        acc[p][0] = pack2(ba.x, ba.x); acc[p][1] = pack2(ba.y, ba.y);
        acc[p][2] = pack2(ba.z, ba.z); acc[p][3] = pack2(ba.w, ba.w);
        acc[p][4] = pack2(bbv.x, bbv.x); acc[p][5] = pack2(bbv.y, bbv.y);
        acc[p][6] = pack2(bbv.z, bbv.z); acc[p][7] = pack2(bbv.w, bbv.w);
    }

    STAGE_W(0, 0);
    __syncthreads();
#pragma unroll
    for (int kc = 0; kc < NC; kc++) {
        if (kc + 1 < NC) STAGE_W(kc + 1, (kc + 1) & 1);
        int b = kc & 1;
#pragma unroll
        for (int k = 0; k < 16; k++) {
            ull a0 = *((const ull*)&As[b][k][ty * 4]);
            ull a1 = *((const ull*)&As[b][k][ty * 4 + 2]);
            float4 wa = *((const float4*)&Wa[b][k][tx * 4]);
            float4 wb = *((const float4*)&Wb[b][k][tx * 4]);
            ull wd[8];
            wd[0] = pack2(wa.x, wa.x); wd[1] = pack2(wa.y, wa.y);
            wd[2] = pack2(wa.z, wa.z); wd[3] = pack2(wa.w, wa.w);
            wd[4] = pack2(wb.x, wb.x); wd[5] = pack2(wb.y, wb.y);
            wd[6] = pack2(wb.z, wb.z); wd[7] = pack2(wb.w, wb.w);
#pragma unroll
            for (int c = 0; c < 8; c++) {
                FFMA2(acc[0][c], a0, wd[c], acc[0][c]);
                FFMA2(acc[1][c], a1, wd[c], acc[1][c]);
            }
        }
        __syncthreads();
    }
#undef STAGE_W

    float ps[8], pq[8];
#pragma unroll
    for (int c = 0; c < 8; c++) { ps[c] = 0.0f; pq[c] = 0.0f; }
#pragma unroll
    for (int p = 0; p < 2; p++) {
        float2 cc[8];
#pragma unroll
        for (int c = 0; c < 8; c++) {
            cc[c] = unpack2(acc[p][c]);
            if (POST_RELU) { cc[c].x = fmaxf(cc[c].x, 0.0f); cc[c].y = fmaxf(cc[c].y, 0.0f); }
        }
        int gr0 = row0 + ty * 4 + 2 * p;
        if (gr0 < NN) {
            *((float4*)(O + (size_t)gr0 * FIN + tx * 4)) = make_float4(cc[0].x, cc[1].x, cc[2].x, cc[3].x);
            *((float4*)(O + (size_t)gr0 * FIN + 64 + tx * 4)) = make_float4(cc[4].x, cc[5].x, cc[6].x, cc[7].x);
            if (STATS)
#pragma unroll
                for (int c = 0; c < 8; c++) { ps[c] += cc[c].x; pq[c] += cc[c].x * cc[c].x; }
        }
        if (gr0 + 1 < NN) {
            *((float4*)(O + (size_t)(gr0 + 1) * FIN + tx * 4)) = make_float4(cc[0].y, cc[1].y, cc[2].y, cc[3].y);
            *((float4*)(O + (size_t)(gr0 + 1) * FIN + 64 + tx * 4)) = make_float4(cc[4].y, cc[5].y, cc[6].y, cc[7].y);
            if (STATS)
#pragma unroll
                for (int c = 0; c < 8; c++) { ps[c] += cc[c].y; pq[c] += cc[c].y * cc[c].y; }
        }
    }
    if (STATS) {
        __syncthreads();
        *((float4*)&Ssum[ty][tx * 4]) = make_float4(ps[0], ps[1], ps[2], ps[3]);
        *((float4*)&Ssum[ty][64 + tx * 4]) = make_float4(ps[4], ps[5], ps[6], ps[7]);
        *((float4*)&Ssq[ty][tx * 4]) = make_float4(pq[0], pq[1], pq[2], pq[3]);
        *((float4*)&Ssq[ty][64 + tx * 4]) = make_float4(pq[4], pq[5], pq[6], pq[7]);
        __syncthreads();
        if (tid < 128) {
            float s = 0.0f;
#pragma unroll
            for (int t = 0; t < 16; t++) s += Ssum[t][tid];
            atomicAdd(&g_sum[slotoff + tid], s);
        } else {
            int c = tid - 128;
            float q = 0.0f;
#pragma unroll
            for (int t = 0; t < 16; t++) q += Ssq[t][c];
            atomicAdd(&g_sumsq[slotoff + c], q);
        }
    }
}

// ---------------- gather v2: 2 nodes/warp (half-warp rows), fused stats ----------------
__global__ void __launch_bounds__(256) k_gather(const float* __restrict__ bbL, int slotoff) {
    int tid = threadIdx.x;
    int lane = tid & 31, wid = tid >> 5;
    int half = lane >> 4, hl = lane & 15;
    int nib = wid * 2 + half;
    int v = blockIdx.x * 16 + nib;
    float dv = g_dinv[v];
    float ws = dv * dv;
    uint2 mv2 = *((const uint2*)&g_mh[(size_t)v * 32 + hl * 2]);
    float2 f0 = __half22float2(*(__half2*)&mv2.x);
    float2 f1 = __half22float2(*(__half2*)&mv2.y);
    float4 acc = make_float4(f0.x * ws, f0.y * ws, f1.x * ws, f1.y * ws);
    int beg = g_offs[v], end = g_offs[v + 1];
    int deg = end - beg;
    int md = max(deg, __shfl_xor_sync(0xffffffffu, deg, 16));
    for (int jj = 0; jj < md; jj += 16) {
        int j = beg + jj;
        int2 e = (j + hl < end) ? g_csr[j + hl] : make_int2(0, 0);
#pragma unroll
        for (int u = 0; u < 16; u++) {
            int idx = __shfl_sync(0xffffffffu, e.x, u, 16);
            float w = __int_as_float(__shfl_sync(0xffffffffu, e.y, u, 16));
            uint2 r = *((const uint2*)&g_mh[(size_t)idx * 32 + hl * 2]);
            float2 a = __half22float2(*(__half2*)&r.x);
            float2 b = __half22float2(*(__half2*)&r.y);
            acc.x = fmaf(w, a.x, acc.x);
            acc.y = fmaf(w, a.y, acc.y);
            acc.z = fmaf(w, b.x, acc.z);
            acc.w = fmaf(w, b.y, acc.w);
        }
    }
    float4 b4 = ((const float4*)bbL)[hl];
    acc.x += b4.x; acc.y += b4.y; acc.z += b4.z; acc.w += b4.w;
    *((float4*)(g_agg + (size_t)v * DD + hl * 4)) = acc;
    __shared__ __align__(16) float s_sum[16][64], s_sq[16][64];
    *((float4*)&s_sum[nib][hl * 4]) = acc;
    *((float4*)&s_sq[nib][hl * 4]) =
        make_float4(acc.x * acc.x, acc.y * acc.y, acc.z * acc.z, acc.w * acc.w);
    __syncthreads();
    if (tid < 64) {
        float s = 0.0f;
#pragma unroll
        for (int r = 0; r < 16; r++) s += s_sum[r][tid];
        atomicAdd(&g_sum[slotoff + tid], s);
    } else if (tid < 128) {
        int c = tid - 64;
        float q = 0.0f;
#pragma unroll
        for (int r = 0; r < 16; r++) q += s_sq[r][c];
        atomicAdd(&g_sumsq[slotoff + c], q);
    }
}

// ---------------- post: elementwise+learner for 64 nodes, then rb-GEMM to g_mh (fp16) ----------------
template <int MODE, int LAST>
__global__ void __launch_bounds__(256) k_post(int slotoff,
                                              const float* __restrict__ gam,
                                              const float* __restrict__ bet,
                                              const float* __restrict__ lw1,
                                              const float* __restrict__ lb1,
                                              const float* __restrict__ lw2,
                                              const float* __restrict__ lb2,
                                              const float* __restrict__ bwn) {
    __shared__ __align__(16) float Hs[64][66];
    __shared__ __align__(16) float Ws[64][64];
    int tid = threadIdx.x;
    int lane = tid & 31, wid = tid >> 5;
    if (!LAST) {
        for (int i = tid; i < 1024; i += 256) {
            int k = i >> 4, c4 = i & 15;
            *((float4*)&Ws[k][c4 * 4]) = ((const float4*)(bwn + (size_t)k * 64))[c4];
        }
    }
    float scx = 1.0f, scy = 1.0f, shx = 0.0f, shy = 0.0f;
    if (MODE == 1) {
        const float ninv = 1.0f / (float)NN;
        float2 su = ((const float2*)(g_sum + slotoff))[lane];
        float2 sq = ((const float2*)(g_sumsq + slotoff))[lane];
        float2 gm = ((const float2*)gam)[lane];
        float2 bt = ((const float2*)bet)[lane];
        float mx = su.x * ninv, my = su.y * ninv;
        scx = gm.x * rsqrtf(sq.x * ninv - mx * mx + BNEPS);
        scy = gm.y * rsqrtf(sq.y * ninv - my * my + BNEPS);
        shx = bt.x - mx * scx;
        shy = bt.y - my * scy;
    }
#pragma unroll
    for (int n = 0; n < 8; n++) {
        int node = blockIdx.x * 64 + wid * 8 + n;
        float2 hv = make_float2(0.0f, 0.0f);
        if (node < NN) {
            float2 a = ((const float2*)(g_agg + (size_t)node * DD))[lane];
            float2 hn;
            if (MODE == 1) {
                hn.x = fmaxf(a.x * scx + shx, 0.0f);
                hn.y = fmaxf(a.y * scy + shy, 0.0f);
            } else {
                hn = a;
            }
            float2 fo = make_float2(0.0f, 0.0f);
            float2 d = hn;
            if (MODE == 1) {
                fo = ((const float2*)(g_fused + (size_t)node * DD))[lane];
                d.x = hn.x - fo.x;
                d.y = hn.y - fo.y;
            }
            float s = learner(d, lane, lw1, lb1, lw2, lb2);
            hv = make_float2(hn.x * s, hn.y * s);
            float2 fn = make_float2(fo.x + hv.x, fo.y + hv.y);
            ((float2*)(g_fused + (size_t)node * DD))[lane] = fn;
        }
        Hs[2 * lane][wid * 8 + n] = hv.x;
        Hs[2 * lane + 1][wid * 8 + n] = hv.y;
    }
    __syncthreads();
    if (LAST) return;
    int tx = tid & 15, ty = tid >> 4;
    ull acc[2][4];
#pragma unroll
    for (int p = 0; p < 2; p++)
#pragma unroll
        for (int c = 0; c < 4; c++) acc[p][c] = 0ull;
#pragma unroll 8
    for (int k = 0; k < 64; k++) {
        ull a0 = *((const ull*)&Hs[k][ty * 4]);
        ull a1 = *((const ull*)&Hs[k][ty * 4 + 2]);
        float4 w = *((const float4*)&Ws[k][tx * 4]);
        ull wd[4];
        wd[0] = pack2(w.x, w.x); wd[1] = pack2(w.y, w.y);
        wd[2] = pack2(w.z, w.z); wd[3] = pack2(w.w, w.w);
#pragma unroll
        for (int c = 0; c < 4; c++) {
            FFMA2(acc[0][c], a0, wd[c], acc[0][c]);
            FFMA2(acc[1][c], a1, wd[c], acc[1][c]);
        }
    }
#pragma unroll
    for (int p = 0; p < 2; p++) {
        float2 c0 = unpack2(acc[p][0]), c1 = unpack2(acc[p][1]);
        float2 c2 = unpack2(acc[p][2]), c3 = unpack2(acc[p][3]);
        int gr0 = blockIdx.x * 64 + ty * 4 + 2 * p;
        if (gr0 < NN) {
            __half2 p0 = __floats2half2_rn(c0.x, c1.x);
            __half2 p1 = __floats2half2_rn(c2.x, c3.x);
            uint2 pk = make_uint2(*(unsigned*)&p0, *(unsigned*)&p1);
            *((uint2*)&g_mh[(size_t)gr0 * 32 + tx * 2]) = pk;
        }
        if (gr0 + 1 < NN) {
            __half2 p0 = __floats2half2_rn(c0.y, c1.y);
            __half2 p1 = __floats2half2_rn(c2.y, c3.y);
            uint2 pk = make_uint2(*(unsigned*)&p0, *(unsigned*)&p1);
            *((uint2*)&g_mh[(size_t)(gr0 + 1) * 32 + tx * 2]) = pk;
        }
    }
}

// ---------------- host orchestration ----------------
extern "C" void kernel_launch(void* const* d_in, const int* in_sizes, int n_in,
                              void* d_out, int out_size) {
    const float* x      = (const float*)d_in[0];
    const int*   ei     = (const int*)d_in[1];
    const float* im_w1  = (const float*)d_in[2];
    const float* im_b1  = (const float*)d_in[3];
    const float* im_g1  = (const float*)d_in[4];
    const float* im_be1 = (const float*)d_in[5];
    const float* im_w2  = (const float*)d_in[6];
    const float* im_b2  = (const float*)d_in[7];
    const float* lw1    = (const float*)d_in[8];
    const float* lb1    = (const float*)d_in[9];
    const float* lw2    = (const float*)d_in[10];
    const float* lb2    = (const float*)d_in[11];
    const float* bw     = (const float*)d_in[12];
    const float* bb     = (const float*)d_in[13];
    const float* bg     = (const float*)d_in[14];
    const float* bbe    = (const float*)d_in[15];
    const float* om_w1  = (const float*)d_in[16];
    const float* om_b1  = (const float*)d_in[17];
    const float* om_w2  = (const float*)d_in[18];
    const float* om_b2  = (const float*)d_in[19];
    float* outp = (float*)d_out;

    const int NB = (NN + 255) / 256;
    const int EB = (EE + 255) / 256;
    const int G128 = (NN + 127) / 128;  // 391
    const int G64 = (NN + 63) / 64;     // 782
    const int GG = NN / 16;             // 3125

    k_prep<<<NB, 256>>>();
    k_count<<<EB, 256>>>(ei);
    k_scanA<<<SCAN_B, 512>>>();
    // slot 4 (profiled): merged input-map GEMM
    k_gemmW<128, 0, 1, -1><<<G64, 256>>>(x, im_w1, im_b1, 0);
    k_scanC<<<SCAN_B, 512>>>();
    k_fill<<<EB, 256>>>(ei);
    k_gemm<128, 1, 0, 2><<<G128, 256>>>(nullptr, im_w2, 64, im_b2, nullptr, 64,
                                        im_g1, im_be1, 0);
    k_post<0, 0><<<G64, 256>>>(0, nullptr, nullptr, lw1, lb1, lw2, lb2, bw);
    for (int li = 0; li < LL; li++) {
        k_gather<<<GG, 256>>>(bb + 64 * li, 128 + 64 * li);
        if (li < LL - 1) {
            k_post<1, 0><<<G64, 256>>>(128 + 64 * li, bg + 64 * li, bbe + 64 * li,
                                       lw1 + (size_t)(li + 1) * 256, lb1 + (li + 1) * 4,
                                       lw2 + (li + 1) * 4, lb2 + (li + 1),
                                       bw + (size_t)(li + 1) * 4096);
        } else {
            k_post<1, 1><<<G64, 256>>>(128 + 64 * li, bg + 64 * li, bbe + 64 * li,
                                       lw1 + (size_t)(li + 1) * 256, lb1 + (li + 1) * 4,
                                       lw2 + (li + 1) * 4, lb2 + (li + 1), nullptr);
        }
    }
    k_gemmW<64, 1, 0, 1><<<G64, 256>>>(nullptr, om_w1, om_b1, 0);
    k_gemm<128, 0, 0, -1><<<G128, 256>>>(nullptr, om_w2, 64, om_b2, outp, 64,
                                         nullptr, nullptr, 0);
}